// round 11
// baseline (speedup 1.0000x reference)
#include <cuda_runtime.h>
#include <math.h>
#include <stdint.h>

// ---------------------------------------------------------------- dims
constexpr int MDIM = 2048, KDIM = 2048, NDIM = 256;

// ---------------------------------------------------------------- tiling
constexpr int BM = 128, BN = 64;
constexpr int THREADS = 512;                 // 16 warps: 4 (m) x 4 (n)
constexpr int STAGES = 3;                    // ring of k128 super-stages
constexpr int PREF = 2;
constexpr int NIT = KDIM / 128;              // 16 outer iterations
constexpr int ROWB = 80;                     // padded row bytes
constexpr int TILE_B = 64 * ROWB;            // 5120 B per 64-row k64 tile
// k64 group layout: A1(128r) A2(128r) B1(64r) B2(64r)
constexpr int OFF_A1 = 0;
constexpr int OFF_A2 = 2 * TILE_B;           // 10240
constexpr int OFF_B1 = 4 * TILE_B;           // 20480
constexpr int OFF_B2 = 5 * TILE_B;           // 25600
constexpr int SUB_B  = 6 * TILE_B;           // 30720 per k64 group
constexpr int STAGE_BYTES = 2 * SUB_B;       // k128 super-stage = 61440
constexpr int SM_STAGE0 = 1024;
constexpr int SMEM_BYTES = SM_STAGE0 + STAGES * STAGE_BYTES;   // 185344

// padded global blobs: [blk64][k64-tile][64 rows][80 B]
constexpr int WBLOB = 32 * 32 * TILE_B;
constexpr int HBLOB = 4 * 32 * TILE_B;
constexpr int TRP = 144;                     // epilogue transpose row bytes

// ---------------------------------------------------------------- scratch
__device__ __align__(128) int8_t g_WhxA1[WBLOB];
__device__ __align__(128) int8_t g_WhxA2[WBLOB];
__device__ __align__(128) int8_t g_WhhA1[WBLOB];
__device__ __align__(128) int8_t g_WhhA2[WBLOB];
__device__ __align__(128) int8_t g_WphA1[WBLOB];
__device__ __align__(128) int8_t g_WphA2[WBLOB];
__device__ __align__(128) int8_t g_xB1[HBLOB];
__device__ __align__(128) int8_t g_xB2[HBLOB];
__device__ __align__(128) int8_t g_h0B1[HBLOB];
__device__ __align__(128) int8_t g_h0B2[HBLOB];
__device__ __align__(128) int8_t g_h1B1[HBLOB];
__device__ __align__(128) int8_t g_h1B2[HBLOB];
__device__ float g_c[MDIM * NDIM];
__device__ float g_p[MDIM * NDIM];
__device__ int   g_maxbits[4];

// ---------------------------------------------------------------- helpers
__device__ __forceinline__ uint32_t smem_u32(const void* p) {
    uint32_t a;
    asm("{ .reg .u64 t; cvta.to.shared.u64 t, %1; cvt.u32.u64 %0, t; }"
        : "=r"(a) : "l"(p));
    return a;
}

__device__ __forceinline__ void mma_s8(int* c, const uint32_t* a,
                                       const uint32_t* b) {
    asm volatile(
        "mma.sync.aligned.m16n8k32.row.col.s32.s8.s8.s32 "
        "{%0,%1,%2,%3}, {%4,%5,%6,%7}, {%8,%9}, {%0,%1,%2,%3};"
        : "+r"(c[0]), "+r"(c[1]), "+r"(c[2]), "+r"(c[3])
        : "r"(a[0]), "r"(a[1]), "r"(a[2]), "r"(a[3]), "r"(b[0]), "r"(b[1]));
}

__device__ __forceinline__ void ldsm_x4(uint32_t* r, uint32_t addr) {
    asm volatile("ldmatrix.sync.aligned.m8n8.x4.shared.b16 {%0,%1,%2,%3}, [%4];"
                 : "=r"(r[0]), "=r"(r[1]), "=r"(r[2]), "=r"(r[3]) : "r"(addr));
}

__device__ __forceinline__ void bulkcp(uint32_t sdst, const void* gsrc,
                                       uint32_t bytes, uint32_t mbar) {
    asm volatile(
        "cp.async.bulk.shared::cta.global.mbarrier::complete_tx::bytes "
        "[%0], [%1], %2, [%3];"
        :: "r"(sdst), "l"(gsrc), "r"(bytes), "r"(mbar) : "memory");
}

__device__ __forceinline__ void mbar_init(uint32_t mbar, uint32_t cnt) {
    asm volatile("mbarrier.init.shared.b64 [%0], %1;"
                 :: "r"(mbar), "r"(cnt) : "memory");
}

__device__ __forceinline__ void mbar_expect_tx(uint32_t mbar, uint32_t bytes) {
    asm volatile("mbarrier.arrive.expect_tx.shared.b64 _, [%0], %1;"
                 :: "r"(mbar), "r"(bytes) : "memory");
}

__device__ __forceinline__ void mbar_wait(uint32_t mb, uint32_t parity) {
    asm volatile(
        "{\n\t.reg .pred P;\n\t"
        "L0_%=:\n\t"
        "mbarrier.try_wait.parity.acquire.cta.shared::cta.b64 P, [%0], %1, 0x989680;\n\t"
        "@P bra.uni L1_%=;\n\t"
        "bra.uni L0_%=;\n\t"
        "L1_%=:\n\t}"
        :: "r"(mb), "r"(parity) : "memory");
}

__device__ __forceinline__ void quant2(float q, int8_t& d1, int8_t& d2) {
    float b1 = rintf(q);
    float b2 = rintf((q - b1) * 256.0f);
    b2 = fminf(fmaxf(b2, -127.0f), 127.0f);
    d1 = (int8_t)(int)b1;
    d2 = (int8_t)(int)b2;
}

// ---------------------------------------------------------------- prep
__global__ void reset_kernel() {
    if (threadIdx.x < 4) g_maxbits[threadIdx.x] = 0;
}

__global__ void maxabs_kernel(const float* __restrict__ w0,
                              const float* __restrict__ w1,
                              const float* __restrict__ w2,
                              const float* __restrict__ x) {
    const int t = blockIdx.y;
    const float* src = (t == 0) ? w0 : (t == 1) ? w1 : (t == 2) ? w2 : x;
    const int len = (t == 3) ? KDIM * NDIM : MDIM * KDIM;
    float m = 0.0f;
    for (int i = blockIdx.x * 256 + threadIdx.x; i < len; i += 2048 * 256)
        m = fmaxf(m, fabsf(src[i]));
    #pragma unroll
    for (int o = 16; o > 0; o >>= 1)
        m = fmaxf(m, __shfl_xor_sync(~0u, m, o));
    if ((threadIdx.x & 31) == 0)
        atomicMax(&g_maxbits[t], __float_as_int(m));
}

__global__ void quant_kernel(const float* __restrict__ w0,
                             const float* __restrict__ w1,
                             const float* __restrict__ w2,
                             const float* __restrict__ x) {
    const int t = blockIdx.y;
    const int len = (t == 3) ? KDIM * NDIM : MDIM * KDIM;
    const int i = blockIdx.x * 256 + threadIdx.x;
    if (i >= len) return;
    const float mx = fmaxf(__int_as_float(g_maxbits[t]), 1e-20f);
    const float iq = 127.0f / mx;
    int8_t d1, d2;
    if (t == 3) {
        const int k = i / NDIM, n = i % NDIM;
        quant2(x[i] * iq, d1, d2);
        const size_t off = (size_t)((n >> 6) * 32 + (k >> 6)) * TILE_B +
                           (n & 63) * ROWB + (k & 63);
        g_xB1[off] = d1;
        g_xB2[off] = d2;
    } else {
        const int m = i >> 11, k = i & 2047;
        const float* w = (t == 0) ? w0 : (t == 1) ? w1 : w2;
        int8_t* o1 = (t == 0) ? g_WhxA1 : (t == 1) ? g_WhhA1 : g_WphA1;
        int8_t* o2 = (t == 0) ? g_WhxA2 : (t == 1) ? g_WhhA2 : g_WphA2;
        quant2(w[i] * iq, d1, d2);
        const size_t off = (size_t)((m >> 6) * 32 + (k >> 6)) * TILE_B +
                           (m & 63) * ROWB + (k & 63);
        o1[off] = d1;
        o2[off] = d2;
    }
}

__global__ void first_step_kernel(const float* __restrict__ c,
                                  const float* __restrict__ bh,
                                  int8_t* __restrict__ outB1,
                                  int8_t* __restrict__ outB2) {
    const int i = blockIdx.x * 256 + threadIdx.x;
    if (i >= MDIM * NDIM) return;
    const int n = i >> 11, m = i & 2047;
    const float v = tanhf(c[(size_t)m * NDIM + n] + bh[n]);
    int8_t d1, d2;
    quant2(v * 127.0f, d1, d2);
    const size_t off = (size_t)((n >> 6) * 32 + (m >> 6)) * TILE_B +
                       (n & 63) * ROWB + (m & 63);
    outB1[off] = d1;
    outB2[off] = d2;
}

// ---------------------------------------------------------------- main GEMM
__global__ void __launch_bounds__(THREADS) rnn_gemm(
    const int8_t* __restrict__ A1, const int8_t* __restrict__ A2,
    const int8_t* __restrict__ B1, const int8_t* __restrict__ B2,
    const int* __restrict__ maxA, const int* __restrict__ maxB,
    const float* __restrict__ addc, const float* __restrict__ bias,
    float* __restrict__ outF,
    int8_t* __restrict__ outB1, int8_t* __restrict__ outB2,
    int mode)
{
    extern __shared__ __align__(16) char sm[];
    const uint32_t sbase = smem_u32(sm);
    const int tid  = threadIdx.x;
    const int lane = tid & 31;
    const int wid  = tid >> 5;
    const int wm0  = (wid & 3) * 32;     // 4 warps in m (32 rows each)
    const int wn0  = (wid >> 2) * 16;    // 4 warps in n (16 cols each)
    const int mblk = blockIdx.y;         // 0..15 (128-row blocks)
    const int nblk = blockIdx.x;         // 0..3
    const int m0   = mblk * BM;
    const int n0   = nblk * BN;
    const int mt64 = mblk * 2;           // first 64-row blob tile index

    const float sa  = __int_as_float(*maxA) * (1.0f / 127.0f);
    const float sb  = maxB ? __int_as_float(*maxB) * (1.0f / 127.0f)
                           : (1.0f / 127.0f);
    const float sAB = sa * sb;

    int C1[2][2][4] = {};
    int C2[2][2][4] = {};

    const uint32_t aoff = (uint32_t)((lane & 15) * ROWB + (lane >> 4) * 16);
    const uint32_t boff = (uint32_t)((lane & 7) * ROWB +
                                     ((lane >> 4) & 1) * 8 * ROWB +
                                     ((lane >> 3) & 1) * 16);

    if (tid == 0) {
        #pragma unroll
        for (int s = 0; s < STAGES; ++s) mbar_init(sbase + s * 8, 1);
        asm volatile("fence.proxy.async.shared::cta;" ::: "memory");
    }
    __syncthreads();

    // one super-stage = two consecutive k64 groups (12 bulk copies, 60 KB)
    auto issue_stage = [&](int it) {
        const int s = it % STAGES;
        const uint32_t mb = sbase + s * 8;
        const uint32_t dst = sbase + SM_STAGE0 + s * STAGE_BYTES;
        mbar_expect_tx(mb, STAGE_BYTES);
        #pragma unroll
        for (int h = 0; h < 2; ++h) {
            const int kt = 2 * it + h;
            const uint32_t d = dst + h * SUB_B;
            bulkcp(d + OFF_A1,          A1 + (size_t)(mt64 * 32 + kt) * TILE_B, TILE_B, mb);
            bulkcp(d + OFF_A1 + TILE_B, A1 + (size_t)((mt64 + 1) * 32 + kt) * TILE_B, TILE_B, mb);
            bulkcp(d + OFF_A2,          A2 + (size_t)(mt64 * 32 + kt) * TILE_B, TILE_B, mb);
            bulkcp(d + OFF_A2 + TILE_B, A2 + (size_t)((mt64 + 1) * 32 + kt) * TILE_B, TILE_B, mb);
            bulkcp(d + OFF_B1, B1 + (size_t)(nblk * 32 + kt) * TILE_B, TILE_B, mb);
            bulkcp(d + OFF_B2, B2 + (size_t)(nblk * 32 + kt) * TILE_B, TILE_B, mb);
        }
    };

    if (tid == 0) {
        #pragma unroll
        for (int s = 0; s < PREF; ++s) issue_stage(s);
    }

    for (int it = 0; it < NIT; ++it) {
        __syncthreads();   // all warps done reading the stage being reissued
        if (tid == 0 && it + PREF < NIT) issue_stage(it + PREF);
        mbar_wait(sbase + (it % STAGES) * 8, (uint32_t)((it / STAGES) & 1));

        const uint32_t st = sbase + SM_STAGE0 + (it % STAGES) * STAGE_BYTES;
        #pragma unroll
        for (int h = 0; h < 2; ++h) {
            const uint32_t sub = st + h * SUB_B;
            const uint32_t sA1 = sub + OFF_A1;
            const uint32_t sA2 = sub + OFF_A2;
            const uint32_t sB1 = sub + OFF_B1;
            const uint32_t sB2 = sub + OFF_B2;
            #pragma unroll
            for (int kk = 0; kk < 2; ++kk) {
                const uint32_t kb = kk * 32;
                uint32_t a1f[2][4], a2f[2][4], b1f[4], b2f[4];
                ldsm_x4(a1f[0], sA1 + (uint32_t)(wm0 * ROWB) + kb + aoff);
                ldsm_x4(a1f[1], sA1 + (uint32_t)((wm0 + 16) * ROWB) + kb + aoff);
                ldsm_x4(a2f[0], sA2 + (uint32_t)(wm0 * ROWB) + kb + aoff);
                ldsm_x4(a2f[1], sA2 + (uint32_t)((wm0 + 16) * ROWB) + kb + aoff);
                ldsm_x4(b1f, sB1 + (uint32_t)(wn0 * ROWB) + kb + boff);
                ldsm_x4(b2f, sB2 + (uint32_t)(wn0 * ROWB) + kb + boff);
                #pragma unroll
                for (int mt = 0; mt < 2; ++mt)
                    #pragma unroll
                    for (int nt = 0; nt < 2; ++nt) {
                        mma_s8(C1[mt][nt], a1f[mt], &b1f[nt * 2]);
                        mma_s8(C2[mt][nt], a1f[mt], &b2f[nt * 2]);
                        mma_s8(C2[mt][nt], a2f[mt], &b1f[nt * 2]);
                    }
            }
        }
    }

    // ------------------------------------------------------------ epilogue
    if (mode == 2) {
        __syncthreads();
        int8_t* th = (int8_t*)sm + SM_STAGE0;             // [64 n][TRP] m-major
        int8_t* tl = (int8_t*)sm + SM_STAGE0 + 64 * TRP;  // [64 n][TRP]
        #pragma unroll
        for (int mt = 0; mt < 2; ++mt)
            #pragma unroll
            for (int nt = 0; nt < 2; ++nt) {
                const int lr = wm0 + mt * 16 + (lane >> 2);   // 0..127
                const int lc = wn0 + nt * 8 + 2 * (lane & 3); // 0..63
                const int gm = m0 + lr, gn = n0 + lc;
                float2 c0 = *(const float2*)(addc + (size_t)gm * NDIM + gn);
                float2 c1 = *(const float2*)(addc + (size_t)(gm + 8) * NDIM + gn);
                float2 bv = *(const float2*)(bias + gn);
                float d00 = sAB * ((float)C1[mt][nt][0] + (float)C2[mt][nt][0] * (1.0f / 256.0f));
                float d01 = sAB * ((float)C1[mt][nt][1] + (float)C2[mt][nt][1] * (1.0f / 256.0f));
                float d10 = sAB * ((float)C1[mt][nt][2] + (float)C2[mt][nt][2] * (1.0f / 256.0f));
                float d11 = sAB * ((float)C1[mt][nt][3] + (float)C2[mt][nt][3] * (1.0f / 256.0f));
                float v00 = tanhf(d00 + c0.x + bv.x) * 127.0f;
                float v01 = tanhf(d01 + c0.y + bv.y) * 127.0f;
                float v10 = tanhf(d10 + c1.x + bv.x) * 127.0f;
                float v11 = tanhf(d11 + c1.y + bv.y) * 127.0f;
                int8_t h, l;
                quant2(v00, h, l); th[lc * TRP + lr] = h;       tl[lc * TRP + lr] = l;
                quant2(v01, h, l); th[(lc + 1) * TRP + lr] = h; tl[(lc + 1) * TRP + lr] = l;
                quant2(v10, h, l); th[lc * TRP + lr + 8] = h;   tl[lc * TRP + lr + 8] = l;
                quant2(v11, h, l); th[(lc + 1) * TRP + lr + 8] = h;
                                   tl[(lc + 1) * TRP + lr + 8] = l;
            }
        __syncthreads();
        // writeout: 2 arrays x 2 mtiles x 64 rows x 4 uint4 = 1024, 2/thread
        #pragma unroll
        for (int j = 0; j < 2; ++j) {
            const int cid = tid + 512 * j;
            const int arr = cid >> 9;
            const int rem = cid & 511;
            const int mt  = rem >> 8;
            const int r2  = rem & 255;
            const int row = r2 >> 2;
            const int q   = r2 & 3;
            const int8_t* src = arr ? tl : th;
            int8_t* dstb = arr ? outB2 : outB1;
            const size_t base = (size_t)((nblk * 32) + mt64 + mt) * TILE_B;
            uint4 v = *(const uint4*)&src[row * TRP + mt * 64 + q * 16];
            *(uint4*)&dstb[base + row * ROWB + q * 16] = v;
        }
    } else {
        #pragma unroll
        for (int mt = 0; mt < 2; ++mt)
            #pragma unroll
            for (int nt = 0; nt < 2; ++nt) {
                const int lr = wm0 + mt * 16 + (lane >> 2);
                const int lc = wn0 + nt * 8 + 2 * (lane & 3);
                const int gm = m0 + lr, gn = n0 + lc;
                float bx = 0.f, by = 0.f;
                if (mode == 1) {
                    float2 bv = *(const float2*)(bias + gn);
                    bx = bv.x; by = bv.y;
                }
                float2 o0, o1;
                o0.x = sAB * ((float)C1[mt][nt][0] + (float)C2[mt][nt][0] * (1.0f / 256.0f)) + bx;
                o0.y = sAB * ((float)C1[mt][nt][1] + (float)C2[mt][nt][1] * (1.0f / 256.0f)) + by;
                o1.x = sAB * ((float)C1[mt][nt][2] + (float)C2[mt][nt][2] * (1.0f / 256.0f)) + bx;
                o1.y = sAB * ((float)C1[mt][nt][3] + (float)C2[mt][nt][3] * (1.0f / 256.0f)) + by;
                *(float2*)(outF + (size_t)gm * NDIM + gn) = o0;
                *(float2*)(outF + (size_t)(gm + 8) * NDIM + gn) = o1;
            }
    }
}

// ---------------------------------------------------------------- softmax
__global__ __launch_bounds__(256) void softmax_kernel(
    const float* __restrict__ p, float* __restrict__ out)
{
    const int row  = blockIdx.x * 8 + (threadIdx.x >> 5);
    const int lane = threadIdx.x & 31;
    const float* pr = p + (size_t)row * NDIM;
    float v[8];
    float mx = -INFINITY;
    #pragma unroll
    for (int i = 0; i < 8; ++i) { v[i] = pr[lane + 32 * i]; mx = fmaxf(mx, v[i]); }
    #pragma unroll
    for (int o = 16; o > 0; o >>= 1) mx = fmaxf(mx, __shfl_xor_sync(~0u, mx, o));
    float s = 0.f;
    #pragma unroll
    for (int i = 0; i < 8; ++i) { v[i] = expf(v[i] - mx); s += v[i]; }
    #pragma unroll
    for (int o = 16; o > 0; o >>= 1) s += __shfl_xor_sync(~0u, s, o);
    const float inv = 1.0f / s;
    float* orow = out + (size_t)row * NDIM;
    #pragma unroll
    for (int i = 0; i < 8; ++i) orow[lane + 32 * i] = v[i] * inv;
}

// ---------------------------------------------------------------- launch
extern "C" void kernel_launch(void* const* d_in, const int* in_sizes, int n_in,
                              void* d_out, int out_size)
{
    const float* x   = (const float*)d_in[0];
    const float* Whx = (const float*)d_in[1];
    const float* Whh = (const float*)d_in[2];
    const float* Wph = (const float*)d_in[3];
    const float* bh  = (const float*)d_in[4];
    const float* bp  = (const float*)d_in[5];

    int8_t *whx1, *whx2, *whh1, *whh2, *wph1, *wph2;
    int8_t *xb1, *xb2, *h0b1, *h0b2, *h1b1, *h1b2;
    float *c, *p;
    int* maxbits;
    cudaGetSymbolAddress((void**)&whx1, g_WhxA1);
    cudaGetSymbolAddress((void**)&whx2, g_WhxA2);
    cudaGetSymbolAddress((void**)&whh1, g_WhhA1);
    cudaGetSymbolAddress((void**)&whh2, g_WhhA2);
    cudaGetSymbolAddress((void**)&wph1, g_WphA1);
    cudaGetSymbolAddress((void**)&wph2, g_WphA2);
    cudaGetSymbolAddress((void**)&xb1,  g_xB1);
    cudaGetSymbolAddress((void**)&xb2,  g_xB2);
    cudaGetSymbolAddress((void**)&h0b1, g_h0B1);
    cudaGetSymbolAddress((void**)&h0b2, g_h0B2);
    cudaGetSymbolAddress((void**)&h1b1, g_h1B1);
    cudaGetSymbolAddress((void**)&h1b2, g_h1B2);
    cudaGetSymbolAddress((void**)&c,    g_c);
    cudaGetSymbolAddress((void**)&p,    g_p);
    cudaGetSymbolAddress((void**)&maxbits, g_maxbits);

    cudaFuncSetAttribute(rnn_gemm, cudaFuncAttributeMaxDynamicSharedMemorySize,
                         SMEM_BYTES);

    reset_kernel<<<1, 32>>>();
    maxabs_kernel<<<dim3(2048, 4), 256>>>(Whx, Whh, Wph, x);
    quant_kernel<<<dim3((MDIM * KDIM + 255) / 256, 4), 256>>>(Whx, Whh, Wph, x);

    const dim3 grid(NDIM / BN, MDIM / BM);   // (4, 16) = 64 CTAs

    // c = Whx @ x
    rnn_gemm<<<grid, THREADS, SMEM_BYTES>>>(whx1, whx2, xb1, xb2,
                                            maxbits + 0, maxbits + 3,
                                            nullptr, nullptr, c,
                                            nullptr, nullptr, 0);

    // step 1: h1 = tanh(c + bh) (h0 = 0)
    first_step_kernel<<<(MDIM * NDIM + 255) / 256, 256>>>(c, bh, h0b1, h0b2);

    // steps 2..256
    int8_t *pb1 = h0b1, *pb2 = h0b2, *nb1 = h1b1, *nb2 = h1b2;
    for (int t = 1; t < NDIM; ++t) {
        rnn_gemm<<<grid, THREADS, SMEM_BYTES>>>(whh1, whh2, pb1, pb2,
                                                maxbits + 1, nullptr,
                                                c, bh, nullptr,
                                                nb1, nb2, 2);
        int8_t* tm;
        tm = pb1; pb1 = nb1; nb1 = tm;
        tm = pb2; pb2 = nb2; nb2 = tm;
    }

    // p = Wph @ h + bp; softmax
    rnn_gemm<<<grid, THREADS, SMEM_BYTES>>>(wph1, wph2, pb1, pb2,
                                            maxbits + 2, nullptr,
                                            nullptr, bp, p,
                                            nullptr, nullptr, 1);
    softmax_kernel<<<MDIM / 8, 256>>>(p, (float*)d_out);
}

// round 12
// speedup vs baseline: 1.3746x; 1.3746x over previous
#include <cuda_runtime.h>
#include <math.h>
#include <stdint.h>

// ---------------------------------------------------------------- dims
constexpr int MDIM = 2048, KDIM = 2048, NDIM = 256;

// ---------------------------------------------------------------- tiling
constexpr int BM = 64, BN = 64;
constexpr int THREADS = 128;                 // 4 warps: 2 (m) x 2 (n), 32x32 each
constexpr int STAGES = 4;                    // ring of k128 super-stages
constexpr int PREF = 3;
constexpr int NIT = KDIM / 128;              // 16 outer iterations
constexpr int ROWB = 80;                     // padded row bytes
constexpr int TILE_B = 64 * ROWB;            // 5120 B per operand k64 tile
constexpr int SUB_B = 4 * TILE_B;            // one k64 group (A1,A2,B1,B2)
constexpr int STAGE_BYTES = 2 * SUB_B;       // k128 super-stage = 40960
constexpr int SM_STAGE0 = 1024;
constexpr int SMEM_BYTES = SM_STAGE0 + STAGES * STAGE_BYTES;   // 164864

// padded global blobs: [blk64][k64-tile][64 rows][80 B]
constexpr int WBLOB = 32 * 32 * TILE_B;
constexpr int HBLOB = 4 * 32 * TILE_B;

// ---------------------------------------------------------------- scratch
__device__ __align__(128) int8_t g_WhxA1[WBLOB];
__device__ __align__(128) int8_t g_WhxA2[WBLOB];
__device__ __align__(128) int8_t g_WhhA1[WBLOB];
__device__ __align__(128) int8_t g_WhhA2[WBLOB];
__device__ __align__(128) int8_t g_WphA1[WBLOB];
__device__ __align__(128) int8_t g_WphA2[WBLOB];
__device__ __align__(128) int8_t g_xB1[HBLOB];
__device__ __align__(128) int8_t g_xB2[HBLOB];
__device__ __align__(128) int8_t g_h0B1[HBLOB];
__device__ __align__(128) int8_t g_h0B2[HBLOB];
__device__ __align__(128) int8_t g_h1B1[HBLOB];
__device__ __align__(128) int8_t g_h1B2[HBLOB];
__device__ float g_c[MDIM * NDIM];
__device__ float g_p[MDIM * NDIM];
__device__ int   g_maxbits[4];

// ---------------------------------------------------------------- helpers
__device__ __forceinline__ uint32_t smem_u32(const void* p) {
    uint32_t a;
    asm("{ .reg .u64 t; cvta.to.shared.u64 t, %1; cvt.u32.u64 %0, t; }"
        : "=r"(a) : "l"(p));
    return a;
}

__device__ __forceinline__ void mma_s8(int* c, const uint32_t* a,
                                       const uint32_t* b) {
    asm volatile(
        "mma.sync.aligned.m16n8k32.row.col.s32.s8.s8.s32 "
        "{%0,%1,%2,%3}, {%4,%5,%6,%7}, {%8,%9}, {%0,%1,%2,%3};"
        : "+r"(c[0]), "+r"(c[1]), "+r"(c[2]), "+r"(c[3])
        : "r"(a[0]), "r"(a[1]), "r"(a[2]), "r"(a[3]), "r"(b[0]), "r"(b[1]));
}

__device__ __forceinline__ void ldsm_x4(uint32_t* r, uint32_t addr) {
    asm volatile("ldmatrix.sync.aligned.m8n8.x4.shared.b16 {%0,%1,%2,%3}, [%4];"
                 : "=r"(r[0]), "=r"(r[1]), "=r"(r[2]), "=r"(r[3]) : "r"(addr));
}

__device__ __forceinline__ void bulkcp(uint32_t sdst, const void* gsrc,
                                       uint32_t bytes, uint32_t mbar) {
    asm volatile(
        "cp.async.bulk.shared::cta.global.mbarrier::complete_tx::bytes "
        "[%0], [%1], %2, [%3];"
        :: "r"(sdst), "l"(gsrc), "r"(bytes), "r"(mbar) : "memory");
}

__device__ __forceinline__ void mbar_init(uint32_t mbar, uint32_t cnt) {
    asm volatile("mbarrier.init.shared.b64 [%0], %1;"
                 :: "r"(mbar), "r"(cnt) : "memory");
}

__device__ __forceinline__ void mbar_expect_tx(uint32_t mbar, uint32_t bytes) {
    asm volatile("mbarrier.arrive.expect_tx.shared.b64 _, [%0], %1;"
                 :: "r"(mbar), "r"(bytes) : "memory");
}

__device__ __forceinline__ void mbar_wait(uint32_t mb, uint32_t parity) {
    asm volatile(
        "{\n\t.reg .pred P;\n\t"
        "L0_%=:\n\t"
        "mbarrier.try_wait.parity.acquire.cta.shared::cta.b64 P, [%0], %1, 0x989680;\n\t"
        "@P bra.uni L1_%=;\n\t"
        "bra.uni L0_%=;\n\t"
        "L1_%=:\n\t}"
        :: "r"(mb), "r"(parity) : "memory");
}

__device__ __forceinline__ void quant2(float q, int8_t& d1, int8_t& d2) {
    float b1 = rintf(q);
    float b2 = rintf((q - b1) * 256.0f);
    b2 = fminf(fmaxf(b2, -127.0f), 127.0f);
    d1 = (int8_t)(int)b1;
    d2 = (int8_t)(int)b2;
}

// ---------------------------------------------------------------- prep
__global__ void reset_kernel() {
    if (threadIdx.x < 4) g_maxbits[threadIdx.x] = 0;
}

__global__ void maxabs_kernel(const float* __restrict__ w0,
                              const float* __restrict__ w1,
                              const float* __restrict__ w2,
                              const float* __restrict__ x) {
    const int t = blockIdx.y;
    const float* src = (t == 0) ? w0 : (t == 1) ? w1 : (t == 2) ? w2 : x;
    const int len = (t == 3) ? KDIM * NDIM : MDIM * KDIM;
    float m = 0.0f;
    for (int i = blockIdx.x * 256 + threadIdx.x; i < len; i += 2048 * 256)
        m = fmaxf(m, fabsf(src[i]));
    #pragma unroll
    for (int o = 16; o > 0; o >>= 1)
        m = fmaxf(m, __shfl_xor_sync(~0u, m, o));
    if ((threadIdx.x & 31) == 0)
        atomicMax(&g_maxbits[t], __float_as_int(m));
}

__global__ void quant_kernel(const float* __restrict__ w0,
                             const float* __restrict__ w1,
                             const float* __restrict__ w2,
                             const float* __restrict__ x) {
    const int t = blockIdx.y;
    const int len = (t == 3) ? KDIM * NDIM : MDIM * KDIM;
    const int i = blockIdx.x * 256 + threadIdx.x;
    if (i >= len) return;
    const float mx = fmaxf(__int_as_float(g_maxbits[t]), 1e-20f);
    const float iq = 127.0f / mx;
    int8_t d1, d2;
    if (t == 3) {
        const int k = i / NDIM, n = i % NDIM;
        quant2(x[i] * iq, d1, d2);
        const size_t off = (size_t)((n >> 6) * 32 + (k >> 6)) * TILE_B +
                           (n & 63) * ROWB + (k & 63);
        g_xB1[off] = d1;
        g_xB2[off] = d2;
    } else {
        const int m = i >> 11, k = i & 2047;
        const float* w = (t == 0) ? w0 : (t == 1) ? w1 : w2;
        int8_t* o1 = (t == 0) ? g_WhxA1 : (t == 1) ? g_WhhA1 : g_WphA1;
        int8_t* o2 = (t == 0) ? g_WhxA2 : (t == 1) ? g_WhhA2 : g_WphA2;
        quant2(w[i] * iq, d1, d2);
        const size_t off = (size_t)((m >> 6) * 32 + (k >> 6)) * TILE_B +
                           (m & 63) * ROWB + (k & 63);
        o1[off] = d1;
        o2[off] = d2;
    }
}

__global__ void first_step_kernel(const float* __restrict__ c,
                                  const float* __restrict__ bh,
                                  int8_t* __restrict__ outB1,
                                  int8_t* __restrict__ outB2) {
    const int i = blockIdx.x * 256 + threadIdx.x;
    if (i >= MDIM * NDIM) return;
    const int n = i >> 11, m = i & 2047;
    const float v = tanhf(c[(size_t)m * NDIM + n] + bh[n]);
    int8_t d1, d2;
    quant2(v * 127.0f, d1, d2);
    const size_t off = (size_t)((n >> 6) * 32 + (m >> 6)) * TILE_B +
                       (n & 63) * ROWB + (m & 63);
    outB1[off] = d1;
    outB2[off] = d2;
}

// ---------------------------------------------------------------- main GEMM
__global__ void __launch_bounds__(THREADS) rnn_gemm(
    const int8_t* __restrict__ A1, const int8_t* __restrict__ A2,
    const int8_t* __restrict__ B1, const int8_t* __restrict__ B2,
    const int* __restrict__ maxA, const int* __restrict__ maxB,
    const float* __restrict__ addc, const float* __restrict__ bias,
    float* __restrict__ outF,
    int8_t* __restrict__ outB1, int8_t* __restrict__ outB2,
    int mode)
{
    extern __shared__ __align__(16) char sm[];
    const uint32_t sbase = smem_u32(sm);
    const int tid  = threadIdx.x;
    const int lane = tid & 31;
    const int wid  = tid >> 5;
    const int wm0  = (wid & 1) * 32;     // 2 warps in m (32 rows each)
    const int wn0  = (wid >> 1) * 32;    // 2 warps in n (32 cols each)
    const int mblk = blockIdx.y;         // 0..31
    const int nblk = blockIdx.x;         // 0..3
    const int m0   = mblk * BM;
    const int n0   = nblk * BN;

    const float sa  = __int_as_float(*maxA) * (1.0f / 127.0f);
    const float sb  = maxB ? __int_as_float(*maxB) * (1.0f / 127.0f)
                           : (1.0f / 127.0f);
    const float sAB = sa * sb;

    int C1[2][4][4] = {};
    int C2[2][4][4] = {};

    const uint32_t aoff = (uint32_t)((lane & 15) * ROWB + (lane >> 4) * 16);
    const uint32_t boff = (uint32_t)((lane & 7) * ROWB +
                                     ((lane >> 4) & 1) * 8 * ROWB +
                                     ((lane >> 3) & 1) * 16);

    if (tid == 0) {
        #pragma unroll
        for (int s = 0; s < STAGES; ++s) mbar_init(sbase + s * 8, 1);
        asm volatile("fence.proxy.async.shared::cta;" ::: "memory");
    }
    __syncthreads();

    // one super-stage = two consecutive k64 groups (8 bulk copies, 40 KB)
    auto issue_stage = [&](int it) {
        const int s = it % STAGES;
        const uint32_t mb = sbase + s * 8;
        const uint32_t dst = sbase + SM_STAGE0 + s * STAGE_BYTES;
        mbar_expect_tx(mb, STAGE_BYTES);
        #pragma unroll
        for (int h = 0; h < 2; ++h) {
            const int kt = 2 * it + h;
            const uint32_t d = dst + h * SUB_B;
            bulkcp(d,              A1 + (size_t)(mblk * 32 + kt) * TILE_B, TILE_B, mb);
            bulkcp(d + TILE_B,     A2 + (size_t)(mblk * 32 + kt) * TILE_B, TILE_B, mb);
            bulkcp(d + 2 * TILE_B, B1 + (size_t)(nblk * 32 + kt) * TILE_B, TILE_B, mb);
            bulkcp(d + 3 * TILE_B, B2 + (size_t)(nblk * 32 + kt) * TILE_B, TILE_B, mb);
        }
    };

    if (tid == 0) {
        #pragma unroll
        for (int s = 0; s < PREF; ++s) issue_stage(s);
    }

    for (int it = 0; it < NIT; ++it) {
        __syncthreads();   // all warps done reading the stage being reissued
        if (tid == 0 && it + PREF < NIT) issue_stage(it + PREF);
        mbar_wait(sbase + (it % STAGES) * 8, (uint32_t)((it / STAGES) & 1));

        const uint32_t st = sbase + SM_STAGE0 + (it % STAGES) * STAGE_BYTES;
        #pragma unroll
        for (int h = 0; h < 2; ++h) {
            const uint32_t sub = st + h * SUB_B;
            const uint32_t sA1 = sub;
            const uint32_t sA2 = sub + TILE_B;
            const uint32_t sB1 = sub + 2 * TILE_B;
            const uint32_t sB2 = sub + 3 * TILE_B;
            #pragma unroll
            for (int kk = 0; kk < 2; ++kk) {
                const uint32_t kb = kk * 32;
                uint32_t a1f[2][4], a2f[2][4], b1f[2][4], b2f[2][4];
                ldsm_x4(a1f[0], sA1 + (uint32_t)(wm0 * ROWB) + kb + aoff);
                ldsm_x4(a1f[1], sA1 + (uint32_t)((wm0 + 16) * ROWB) + kb + aoff);
                ldsm_x4(a2f[0], sA2 + (uint32_t)(wm0 * ROWB) + kb + aoff);
                ldsm_x4(a2f[1], sA2 + (uint32_t)((wm0 + 16) * ROWB) + kb + aoff);
                ldsm_x4(b1f[0], sB1 + (uint32_t)(wn0 * ROWB) + kb + boff);
                ldsm_x4(b1f[1], sB1 + (uint32_t)((wn0 + 16) * ROWB) + kb + boff);
                ldsm_x4(b2f[0], sB2 + (uint32_t)(wn0 * ROWB) + kb + boff);
                ldsm_x4(b2f[1], sB2 + (uint32_t)((wn0 + 16) * ROWB) + kb + boff);
                #pragma unroll
                for (int mt = 0; mt < 2; ++mt)
                    #pragma unroll
                    for (int nt = 0; nt < 4; ++nt) {
                        const uint32_t* bp1 = &b1f[nt >> 1][(nt & 1) * 2];
                        const uint32_t* bp2 = &b2f[nt >> 1][(nt & 1) * 2];
                        mma_s8(C1[mt][nt], a1f[mt], bp1);
                        mma_s8(C2[mt][nt], a1f[mt], bp2);
                        mma_s8(C2[mt][nt], a2f[mt], bp1);
                    }
            }
        }
    }

    // ------------------------------------------------------------ epilogue
    if (mode == 2) {
        __syncthreads();
        int8_t* th = (int8_t*)sm + SM_STAGE0;              // [64 n][80]
        int8_t* tl = (int8_t*)sm + SM_STAGE0 + 64 * ROWB;  // [64 n][80]
        #pragma unroll
        for (int mt = 0; mt < 2; ++mt)
            #pragma unroll
            for (int nt = 0; nt < 4; ++nt) {
                const int lr = wm0 + mt * 16 + (lane >> 2);
                const int lc = wn0 + nt * 8 + 2 * (lane & 3);
                const int gm = m0 + lr, gn = n0 + lc;
                float2 c0 = *(const float2*)(addc + (size_t)gm * NDIM + gn);
                float2 c1 = *(const float2*)(addc + (size_t)(gm + 8) * NDIM + gn);
                float2 bv = *(const float2*)(bias + gn);
                float d00 = sAB * ((float)C1[mt][nt][0] + (float)C2[mt][nt][0] * (1.0f / 256.0f));
                float d01 = sAB * ((float)C1[mt][nt][1] + (float)C2[mt][nt][1] * (1.0f / 256.0f));
                float d10 = sAB * ((float)C1[mt][nt][2] + (float)C2[mt][nt][2] * (1.0f / 256.0f));
                float d11 = sAB * ((float)C1[mt][nt][3] + (float)C2[mt][nt][3] * (1.0f / 256.0f));
                float v00 = tanhf(d00 + c0.x + bv.x) * 127.0f;
                float v01 = tanhf(d01 + c0.y + bv.y) * 127.0f;
                float v10 = tanhf(d10 + c1.x + bv.x) * 127.0f;
                float v11 = tanhf(d11 + c1.y + bv.y) * 127.0f;
                int8_t h, l;
                quant2(v00, h, l); th[lc * ROWB + lr] = h;       tl[lc * ROWB + lr] = l;
                quant2(v01, h, l); th[(lc + 1) * ROWB + lr] = h; tl[(lc + 1) * ROWB + lr] = l;
                quant2(v10, h, l); th[lc * ROWB + lr + 8] = h;   tl[lc * ROWB + lr + 8] = l;
                quant2(v11, h, l); th[(lc + 1) * ROWB + lr + 8] = h;
                                   tl[(lc + 1) * ROWB + lr + 8] = l;
            }
        __syncthreads();
        // writeout: 2 arrays x 64 rows x 4 uint4 = 512 chunks, 4 per thread
        const size_t base = (size_t)(nblk * 32 + mblk) * TILE_B;
        #pragma unroll
        for (int j = 0; j < 4; ++j) {
            const int cid = tid + 128 * j;
            const int arr = cid >> 8;
            const int rq  = cid & 255;
            const int row = rq >> 2;
            const int q   = rq & 3;
            const int8_t* src = arr ? tl : th;
            int8_t* dstb = arr ? outB2 : outB1;
            uint4 v = *(const uint4*)&src[row * ROWB + q * 16];
            *(uint4*)&dstb[base + row * ROWB + q * 16] = v;
        }
    } else {
        #pragma unroll
        for (int mt = 0; mt < 2; ++mt)
            #pragma unroll
            for (int nt = 0; nt < 4; ++nt) {
                const int lr = wm0 + mt * 16 + (lane >> 2);
                const int lc = wn0 + nt * 8 + 2 * (lane & 3);
                const int gm = m0 + lr, gn = n0 + lc;
                float bx = 0.f, by = 0.f;
                if (mode == 1) {
                    float2 bv = *(const float2*)(bias + gn);
                    bx = bv.x; by = bv.y;
                }
                float2 o0, o1;
                o0.x = sAB * ((float)C1[mt][nt][0] + (float)C2[mt][nt][0] * (1.0f / 256.0f)) + bx;
                o0.y = sAB * ((float)C1[mt][nt][1] + (float)C2[mt][nt][1] * (1.0f / 256.0f)) + by;
                o1.x = sAB * ((float)C1[mt][nt][2] + (float)C2[mt][nt][2] * (1.0f / 256.0f)) + bx;
                o1.y = sAB * ((float)C1[mt][nt][3] + (float)C2[mt][nt][3] * (1.0f / 256.0f)) + by;
                *(float2*)(outF + (size_t)gm * NDIM + gn) = o0;
                *(float2*)(outF + (size_t)(gm + 8) * NDIM + gn) = o1;
            }
    }
}

// ---------------------------------------------------------------- softmax
__global__ __launch_bounds__(256) void softmax_kernel(
    const float* __restrict__ p, float* __restrict__ out)
{
    const int row  = blockIdx.x * 8 + (threadIdx.x >> 5);
    const int lane = threadIdx.x & 31;
    const float* pr = p + (size_t)row * NDIM;
    float v[8];
    float mx = -INFINITY;
    #pragma unroll
    for (int i = 0; i < 8; ++i) { v[i] = pr[lane + 32 * i]; mx = fmaxf(mx, v[i]); }
    #pragma unroll
    for (int o = 16; o > 0; o >>= 1) mx = fmaxf(mx, __shfl_xor_sync(~0u, mx, o));
    float s = 0.f;
    #pragma unroll
    for (int i = 0; i < 8; ++i) { v[i] = expf(v[i] - mx); s += v[i]; }
    #pragma unroll
    for (int o = 16; o > 0; o >>= 1) s += __shfl_xor_sync(~0u, s, o);
    const float inv = 1.0f / s;
    float* orow = out + (size_t)row * NDIM;
    #pragma unroll
    for (int i = 0; i < 8; ++i) orow[lane + 32 * i] = v[i] * inv;
}

// ---------------------------------------------------------------- launch
extern "C" void kernel_launch(void* const* d_in, const int* in_sizes, int n_in,
                              void* d_out, int out_size)
{
    const float* x   = (const float*)d_in[0];
    const float* Whx = (const float*)d_in[1];
    const float* Whh = (const float*)d_in[2];
    const float* Wph = (const float*)d_in[3];
    const float* bh  = (const float*)d_in[4];
    const float* bp  = (const float*)d_in[5];

    int8_t *whx1, *whx2, *whh1, *whh2, *wph1, *wph2;
    int8_t *xb1, *xb2, *h0b1, *h0b2, *h1b1, *h1b2;
    float *c, *p;
    int* maxbits;
    cudaGetSymbolAddress((void**)&whx1, g_WhxA1);
    cudaGetSymbolAddress((void**)&whx2, g_WhxA2);
    cudaGetSymbolAddress((void**)&whh1, g_WhhA1);
    cudaGetSymbolAddress((void**)&whh2, g_WhhA2);
    cudaGetSymbolAddress((void**)&wph1, g_WphA1);
    cudaGetSymbolAddress((void**)&wph2, g_WphA2);
    cudaGetSymbolAddress((void**)&xb1,  g_xB1);
    cudaGetSymbolAddress((void**)&xb2,  g_xB2);
    cudaGetSymbolAddress((void**)&h0b1, g_h0B1);
    cudaGetSymbolAddress((void**)&h0b2, g_h0B2);
    cudaGetSymbolAddress((void**)&h1b1, g_h1B1);
    cudaGetSymbolAddress((void**)&h1b2, g_h1B2);
    cudaGetSymbolAddress((void**)&c,    g_c);
    cudaGetSymbolAddress((void**)&p,    g_p);
    cudaGetSymbolAddress((void**)&maxbits, g_maxbits);

    cudaFuncSetAttribute(rnn_gemm, cudaFuncAttributeMaxDynamicSharedMemorySize,
                         SMEM_BYTES);

    reset_kernel<<<1, 32>>>();
    maxabs_kernel<<<dim3(2048, 4), 256>>>(Whx, Whh, Wph, x);
    quant_kernel<<<dim3((MDIM * KDIM + 255) / 256, 4), 256>>>(Whx, Whh, Wph, x);

    const dim3 grid(NDIM / BN, MDIM / BM);   // (4, 32) = 128 CTAs

    // c = Whx @ x
    rnn_gemm<<<grid, THREADS, SMEM_BYTES>>>(whx1, whx2, xb1, xb2,
                                            maxbits + 0, maxbits + 3,
                                            nullptr, nullptr, c,
                                            nullptr, nullptr, 0);

    // step 1: h1 = tanh(c + bh) (h0 = 0)
    first_step_kernel<<<(MDIM * NDIM + 255) / 256, 256>>>(c, bh, h0b1, h0b2);

    // steps 2..256
    int8_t *pb1 = h0b1, *pb2 = h0b2, *nb1 = h1b1, *nb2 = h1b2;
    for (int t = 1; t < NDIM; ++t) {
        rnn_gemm<<<grid, THREADS, SMEM_BYTES>>>(whh1, whh2, pb1, pb2,
                                                maxbits + 1, nullptr,
                                                c, bh, nullptr,
                                                nb1, nb2, 2);
        int8_t* tm;
        tm = pb1; pb1 = nb1; nb1 = tm;
        tm = pb2; pb2 = nb2; nb2 = tm;
    }

    // p = Wph @ h + bp; softmax
    rnn_gemm<<<grid, THREADS, SMEM_BYTES>>>(wph1, wph2, pb1, pb2,
                                            maxbits + 2, nullptr,
                                            nullptr, bp, p,
                                            nullptr, nullptr, 1);
    softmax_kernel<<<MDIM / 8, 256>>>(p, (float*)d_out);
}

// round 13
// speedup vs baseline: 1.5052x; 1.0951x over previous
#include <cuda_runtime.h>
#include <math.h>
#include <stdint.h>

// ---------------------------------------------------------------- dims
constexpr int MDIM = 2048, KDIM = 2048, NDIM = 256;

// ---------------------------------------------------------------- tiling
constexpr int BM = 64, BN = 64;
constexpr int THREADS = 512;                 // 16 warps: 4 (m) x 4 (n)
constexpr int STAGES = 5;                    // k128 super-stages
constexpr int PREF = 4;
constexpr int NIT = KDIM / 128;              // 16
// packed swizzled tile: 64 rows x 64 B = 4096 B
constexpr int TILE_B = 4096;
constexpr int KT_B   = 2 * TILE_B;           // digit1|digit2 per k64 = 8192
constexpr int BLK_B  = 32 * KT_B;            // per 64-row block = 262144
constexpr int STAGE_BYTES = 4 * KT_B;        // A(k128) + B(k128) = 32768
constexpr int SM_STAGE0 = 1024;
constexpr int SMEM_BYTES = SM_STAGE0 + STAGES * STAGE_BYTES;   // 164864

// blobs: [blk64][k64][digit1 4K | digit2 4K]
constexpr size_t WBLOB = 32ull * BLK_B;      // 8 MB per weight
constexpr size_t HBLOB = 4ull * BLK_B;       // 1 MB per h/x

// ---------------------------------------------------------------- scratch
__device__ __align__(128) int8_t g_Whx[WBLOB];
__device__ __align__(128) int8_t g_Whh[WBLOB];
__device__ __align__(128) int8_t g_Wph[WBLOB];
__device__ __align__(128) int8_t g_x [HBLOB];
__device__ __align__(128) int8_t g_h0[HBLOB];
__device__ __align__(128) int8_t g_h1[HBLOB];
__device__ float g_c[MDIM * NDIM];
__device__ float g_p[MDIM * NDIM];
__device__ int   g_maxbits[4];

// swizzled byte offset within a packed tile: logical (row, col) 64x64
__device__ __forceinline__ uint32_t tswz(int row, int col) {
    return (uint32_t)(row * 64 + (((col & 48) ^ (((row >> 1) & 3) << 4)) |
                                  (col & 15)));
}

// ---------------------------------------------------------------- helpers
__device__ __forceinline__ uint32_t smem_u32(const void* p) {
    uint32_t a;
    asm("{ .reg .u64 t; cvta.to.shared.u64 t, %1; cvt.u32.u64 %0, t; }"
        : "=r"(a) : "l"(p));
    return a;
}

__device__ __forceinline__ void mma_s8(int* c, const uint32_t* a,
                                       const uint32_t* b) {
    asm volatile(
        "mma.sync.aligned.m16n8k32.row.col.s32.s8.s8.s32 "
        "{%0,%1,%2,%3}, {%4,%5,%6,%7}, {%8,%9}, {%0,%1,%2,%3};"
        : "+r"(c[0]), "+r"(c[1]), "+r"(c[2]), "+r"(c[3])
        : "r"(a[0]), "r"(a[1]), "r"(a[2]), "r"(a[3]), "r"(b[0]), "r"(b[1]));
}

__device__ __forceinline__ void ldsm_x4(uint32_t* r, uint32_t addr) {
    asm volatile("ldmatrix.sync.aligned.m8n8.x4.shared.b16 {%0,%1,%2,%3}, [%4];"
                 : "=r"(r[0]), "=r"(r[1]), "=r"(r[2]), "=r"(r[3]) : "r"(addr));
}

__device__ __forceinline__ void bulkcp(uint32_t sdst, const void* gsrc,
                                       uint32_t bytes, uint32_t mbar) {
    asm volatile(
        "cp.async.bulk.shared::cta.global.mbarrier::complete_tx::bytes "
        "[%0], [%1], %2, [%3];"
        :: "r"(sdst), "l"(gsrc), "r"(bytes), "r"(mbar) : "memory");
}

__device__ __forceinline__ void mbar_init(uint32_t mbar, uint32_t cnt) {
    asm volatile("mbarrier.init.shared.b64 [%0], %1;"
                 :: "r"(mbar), "r"(cnt) : "memory");
}

__device__ __forceinline__ void mbar_expect_tx(uint32_t mbar, uint32_t bytes) {
    asm volatile("mbarrier.arrive.expect_tx.shared.b64 _, [%0], %1;"
                 :: "r"(mbar), "r"(bytes) : "memory");
}

__device__ __forceinline__ void mbar_wait(uint32_t mb, uint32_t parity) {
    asm volatile(
        "{\n\t.reg .pred P;\n\t"
        "L0_%=:\n\t"
        "mbarrier.try_wait.parity.acquire.cta.shared::cta.b64 P, [%0], %1, 0x989680;\n\t"
        "@P bra.uni L1_%=;\n\t"
        "bra.uni L0_%=;\n\t"
        "L1_%=:\n\t}"
        :: "r"(mb), "r"(parity) : "memory");
}

__device__ __forceinline__ void quant2(float q, int8_t& d1, int8_t& d2) {
    float b1 = rintf(q);
    float b2 = rintf((q - b1) * 256.0f);
    b2 = fminf(fmaxf(b2, -127.0f), 127.0f);
    d1 = (int8_t)(int)b1;
    d2 = (int8_t)(int)b2;
}

// ---------------------------------------------------------------- prep
__global__ void reset_kernel() {
    if (threadIdx.x < 4) g_maxbits[threadIdx.x] = 0;
}

__global__ void maxabs_kernel(const float* __restrict__ w0,
                              const float* __restrict__ w1,
                              const float* __restrict__ w2,
                              const float* __restrict__ x) {
    const int t = blockIdx.y;
    const float* src = (t == 0) ? w0 : (t == 1) ? w1 : (t == 2) ? w2 : x;
    const int len = (t == 3) ? KDIM * NDIM : MDIM * KDIM;
    float m = 0.0f;
    for (int i = blockIdx.x * 256 + threadIdx.x; i < len; i += 2048 * 256)
        m = fmaxf(m, fabsf(src[i]));
    #pragma unroll
    for (int o = 16; o > 0; o >>= 1)
        m = fmaxf(m, __shfl_xor_sync(~0u, m, o));
    if ((threadIdx.x & 31) == 0)
        atomicMax(&g_maxbits[t], __float_as_int(m));
}

__global__ void quant_kernel(const float* __restrict__ w0,
                             const float* __restrict__ w1,
                             const float* __restrict__ w2,
                             const float* __restrict__ x) {
    const int t = blockIdx.y;
    const int len = (t == 3) ? KDIM * NDIM : MDIM * KDIM;
    const int i = blockIdx.x * 256 + threadIdx.x;
    if (i >= len) return;
    const float mx = fmaxf(__int_as_float(g_maxbits[t]), 1e-20f);
    const float iq = 127.0f / mx;
    int8_t d1, d2;
    if (t == 3) {
        // x[k][n] -> blob row=n, col=k
        const int k = i / NDIM, n = i % NDIM;
        quant2(x[i] * iq, d1, d2);
        const size_t off = (size_t)(n >> 6) * BLK_B + (size_t)(k >> 6) * KT_B +
                           tswz(n & 63, k & 63);
        g_x[off] = d1;
        g_x[off + TILE_B] = d2;
    } else {
        // W[m][k] -> blob row=m, col=k
        const int m = i >> 11, k = i & 2047;
        const float* w = (t == 0) ? w0 : (t == 1) ? w1 : w2;
        int8_t* o = (t == 0) ? g_Whx : (t == 1) ? g_Whh : g_Wph;
        quant2(w[i] * iq, d1, d2);
        const size_t off = (size_t)(m >> 6) * BLK_B + (size_t)(k >> 6) * KT_B +
                           tswz(m & 63, k & 63);
        o[off] = d1;
        o[off + TILE_B] = d2;
    }
}

// step 1 (h0 = 0): h1 = tanh(c + bh) -> h blob (row=n, col=m)
__global__ void first_step_kernel(const float* __restrict__ c,
                                  const float* __restrict__ bh,
                                  int8_t* __restrict__ outH) {
    const int i = blockIdx.x * 256 + threadIdx.x;
    if (i >= MDIM * NDIM) return;
    const int n = i >> 11, m = i & 2047;
    const float v = tanhf(c[(size_t)m * NDIM + n] + bh[n]);
    int8_t d1, d2;
    quant2(v * 127.0f, d1, d2);
    const size_t off = (size_t)(n >> 6) * BLK_B + (size_t)(m >> 6) * KT_B +
                       tswz(n & 63, m & 63);
    outH[off] = d1;
    outH[off + TILE_B] = d2;
}

// ---------------------------------------------------------------- main GEMM
// D = sA*sB*(A1@B1 + (A1@B2 + A2@B1)/256); blobs [blk][k64][d1|d2] swizzled.
// mode 0: outF = D     mode 1: outF = D + bias
// mode 2: v = tanh(D + addc + bias); quant2(v*127) -> outH blob
__global__ void __launch_bounds__(THREADS) rnn_gemm(
    const int8_t* __restrict__ A, const int8_t* __restrict__ B,
    const int* __restrict__ maxA, const int* __restrict__ maxB,
    const float* __restrict__ addc, const float* __restrict__ bias,
    float* __restrict__ outF, int8_t* __restrict__ outH, int mode)
{
    extern __shared__ __align__(16) char sm[];
    const uint32_t sbase = smem_u32(sm);
    const int tid  = threadIdx.x;
    const int lane = tid & 31;
    const int wid  = tid >> 5;
    const int wm0  = (wid & 3) * 16;     // 4 warps in m
    const int wn0  = (wid >> 2) * 16;    // 4 warps in n
    const int mblk = blockIdx.y;         // 0..31
    const int nblk = blockIdx.x;         // 0..3
    const int m0   = mblk * BM;
    const int n0   = nblk * BN;

    const float sa  = __int_as_float(*maxA) * (1.0f / 127.0f);
    const float sb  = maxB ? __int_as_float(*maxB) * (1.0f / 127.0f)
                           : (1.0f / 127.0f);
    const float sAB = sa * sb;

    int C1[2][4] = {};
    int C2[2][4] = {};

    // per-lane ldsm address pieces (packed swizzled tiles)
    const uint32_t arow = (uint32_t)((wm0 + (lane & 15)) * 64);
    const uint32_t achk = (uint32_t)((lane >> 4) * 16);
    const uint32_t aswz = (uint32_t)((((lane & 15) >> 1) & 3) << 4);
    const uint32_t brow = (uint32_t)((wn0 + (lane & 7) + ((lane >> 4) & 1) * 8) * 64);
    const uint32_t bchk = (uint32_t)(((lane >> 3) & 1) * 16);
    const uint32_t bswz = (uint32_t)(((((lane & 7) + ((lane >> 4) & 1) * 8) >> 1) & 3) << 4);

    if (tid == 0) {
        #pragma unroll
        for (int s = 0; s < STAGES; ++s) mbar_init(sbase + s * 8, 1);
        asm volatile("fence.proxy.async.shared::cta;" ::: "memory");
    }
    __syncthreads();

    // stage = A k128 group (16 KB) + B k128 group (16 KB): 2 bulk copies
    auto issue_stage = [&](int it) {
        const int s = it % STAGES;
        const uint32_t mb = sbase + s * 8;
        const uint32_t dst = sbase + SM_STAGE0 + s * STAGE_BYTES;
        mbar_expect_tx(mb, STAGE_BYTES);
        bulkcp(dst, A + (size_t)mblk * BLK_B + (size_t)(2 * it) * KT_B,
               2 * KT_B, mb);
        bulkcp(dst + 2 * KT_B, B + (size_t)nblk * BLK_B + (size_t)(2 * it) * KT_B,
               2 * KT_B, mb);
    };

    if (tid == 0) {
        #pragma unroll
        for (int s = 0; s < PREF; ++s) issue_stage(s);
    }

    for (int it = 0; it < NIT; ++it) {
        __syncthreads();   // all warps done reading the stage being reissued
        if (tid == 0 && it + PREF < NIT) issue_stage(it + PREF);
        mbar_wait(sbase + (it % STAGES) * 8, (uint32_t)((it / STAGES) & 1));

        const uint32_t st = sbase + SM_STAGE0 + (it % STAGES) * STAGE_BYTES;
        #pragma unroll
        for (int h = 0; h < 2; ++h) {
            const uint32_t sA1 = st + h * KT_B;
            const uint32_t sA2 = sA1 + TILE_B;
            const uint32_t sB1 = st + 2 * KT_B + h * KT_B;
            const uint32_t sB2 = sB1 + TILE_B;
            #pragma unroll
            for (int kk = 0; kk < 2; ++kk) {
                const uint32_t ka = ((kk * 32) | achk) ^ aswz;
                const uint32_t kb2 = ((kk * 32) | bchk) ^ bswz;
                uint32_t a1f[4], a2f[4], b1f[4], b2f[4];
                ldsm_x4(a1f, sA1 + arow + ka);
                ldsm_x4(a2f, sA2 + arow + ka);
                ldsm_x4(b1f, sB1 + brow + kb2);
                ldsm_x4(b2f, sB2 + brow + kb2);
                #pragma unroll
                for (int nt = 0; nt < 2; ++nt) {
                    mma_s8(C1[nt], a1f, &b1f[nt * 2]);
                    mma_s8(C2[nt], a1f, &b2f[nt * 2]);
                    mma_s8(C2[nt], a2f, &b1f[nt * 2]);
                }
            }
        }
    }

    // ------------------------------------------------------------ epilogue
    if (mode == 2) {
        __syncthreads();
        // staging: digit1 tile at SM_STAGE0, digit2 at +TILE_B (blob order)
        int8_t* stg = (int8_t*)sm + SM_STAGE0;
        #pragma unroll
        for (int nt = 0; nt < 2; ++nt) {
            const int lr = wm0 + (lane >> 2);            // m local
            const int lc = wn0 + nt * 8 + 2 * (lane & 3); // n local
            const int gm = m0 + lr, gn = n0 + lc;
            float2 c0 = *(const float2*)(addc + (size_t)gm * NDIM + gn);
            float2 c1 = *(const float2*)(addc + (size_t)(gm + 8) * NDIM + gn);
            float2 bv = *(const float2*)(bias + gn);
            float vv[4];
            vv[0] = tanhf(sAB * ((float)C1[nt][0] + (float)C2[nt][0] * (1.0f / 256.0f)) + c0.x + bv.x) * 127.0f;
            vv[1] = tanhf(sAB * ((float)C1[nt][1] + (float)C2[nt][1] * (1.0f / 256.0f)) + c0.y + bv.y) * 127.0f;
            vv[2] = tanhf(sAB * ((float)C1[nt][2] + (float)C2[nt][2] * (1.0f / 256.0f)) + c1.x + bv.x) * 127.0f;
            vv[3] = tanhf(sAB * ((float)C1[nt][3] + (float)C2[nt][3] * (1.0f / 256.0f)) + c1.y + bv.y) * 127.0f;
            #pragma unroll
            for (int q = 0; q < 4; ++q) {
                const int r = lr + (q >> 1) * 8;     // m local (blob col)
                const int cc = lc + (q & 1);          // n local (blob row)
                int8_t d1, d2;
                quant2(vv[q], d1, d2);
                const uint32_t o = tswz(cc, r);
                stg[o] = d1;
                stg[o + TILE_B] = d2;
            }
        }
        __syncthreads();
        // writeout: 8 KB contiguous (blob order), 512 x uint4
        int8_t* dstb = outH + (size_t)nblk * BLK_B + (size_t)mblk * KT_B;
        *(uint4*)&dstb[tid * 16] = *(const uint4*)&stg[tid * 16];
    } else {
        #pragma unroll
        for (int nt = 0; nt < 2; ++nt) {
            const int lr = wm0 + (lane >> 2);
            const int lc = wn0 + nt * 8 + 2 * (lane & 3);
            const int gm = m0 + lr, gn = n0 + lc;
            float bx = 0.f, by = 0.f;
            if (mode == 1) {
                float2 bv = *(const float2*)(bias + gn);
                bx = bv.x; by = bv.y;
            }
            float2 o0, o1;
            o0.x = sAB * ((float)C1[nt][0] + (float)C2[nt][0] * (1.0f / 256.0f)) + bx;
            o0.y = sAB * ((float)C1[nt][1] + (float)C2[nt][1] * (1.0f / 256.0f)) + by;
            o1.x = sAB * ((float)C1[nt][2] + (float)C2[nt][2] * (1.0f / 256.0f)) + bx;
            o1.y = sAB * ((float)C1[nt][3] + (float)C2[nt][3] * (1.0f / 256.0f)) + by;
            *(float2*)(outF + (size_t)gm * NDIM + gn) = o0;
            *(float2*)(outF + (size_t)(gm + 8) * NDIM + gn) = o1;
        }
    }
}

// ---------------------------------------------------------------- softmax
__global__ __launch_bounds__(256) void softmax_kernel(
    const float* __restrict__ p, float* __restrict__ out)
{
    const int row  = blockIdx.x * 8 + (threadIdx.x >> 5);
    const int lane = threadIdx.x & 31;
    const float* pr = p + (size_t)row * NDIM;
    float v[8];
    float mx = -INFINITY;
    #pragma unroll
    for (int i = 0; i < 8; ++i) { v[i] = pr[lane + 32 * i]; mx = fmaxf(mx, v[i]); }
    #pragma unroll
    for (int o = 16; o > 0; o >>= 1) mx = fmaxf(mx, __shfl_xor_sync(~0u, mx, o));
    float s = 0.f;
    #pragma unroll
    for (int i = 0; i < 8; ++i) { v[i] = expf(v[i] - mx); s += v[i]; }
    #pragma unroll
    for (int o = 16; o > 0; o >>= 1) s += __shfl_xor_sync(~0u, s, o);
    const float inv = 1.0f / s;
    float* orow = out + (size_t)row * NDIM;
    #pragma unroll
    for (int i = 0; i < 8; ++i) orow[lane + 32 * i] = v[i] * inv;
}

// ---------------------------------------------------------------- launch
extern "C" void kernel_launch(void* const* d_in, const int* in_sizes, int n_in,
                              void* d_out, int out_size)
{
    const float* x   = (const float*)d_in[0];
    const float* Whx = (const float*)d_in[1];
    const float* Whh = (const float*)d_in[2];
    const float* Wph = (const float*)d_in[3];
    const float* bh  = (const float*)d_in[4];
    const float* bp  = (const float*)d_in[5];

    int8_t *whx, *whh, *wph, *xb, *h0, *h1;
    float *c, *p;
    int* maxbits;
    cudaGetSymbolAddress((void**)&whx, g_Whx);
    cudaGetSymbolAddress((void**)&whh, g_Whh);
    cudaGetSymbolAddress((void**)&wph, g_Wph);
    cudaGetSymbolAddress((void**)&xb,  g_x);
    cudaGetSymbolAddress((void**)&h0,  g_h0);
    cudaGetSymbolAddress((void**)&h1,  g_h1);
    cudaGetSymbolAddress((void**)&c,   g_c);
    cudaGetSymbolAddress((void**)&p,   g_p);
    cudaGetSymbolAddress((void**)&maxbits, g_maxbits);

    cudaFuncSetAttribute(rnn_gemm, cudaFuncAttributeMaxDynamicSharedMemorySize,
                         SMEM_BYTES);

    reset_kernel<<<1, 32>>>();
    maxabs_kernel<<<dim3(2048, 4), 256>>>(Whx, Whh, Wph, x);
    quant_kernel<<<dim3((MDIM * KDIM + 255) / 256, 4), 256>>>(Whx, Whh, Wph, x);

    const dim3 grid(NDIM / BN, MDIM / BM);   // (4, 32) = 128 CTAs

    // c = Whx @ x
    rnn_gemm<<<grid, THREADS, SMEM_BYTES>>>(whx, xb, maxbits + 0, maxbits + 3,
                                            nullptr, nullptr, c, nullptr, 0);

    // step 1: h1 = tanh(c + bh) (h0 = 0)
    first_step_kernel<<<(MDIM * NDIM + 255) / 256, 256>>>(c, bh, h0);

    // steps 2..256
    int8_t *ph = h0, *pn = h1;
    for (int t = 1; t < NDIM; ++t) {
        rnn_gemm<<<grid, THREADS, SMEM_BYTES>>>(whh, ph, maxbits + 1, nullptr,
                                                c, bh, nullptr, pn, 2);
        int8_t* tm = ph; ph = pn; pn = tm;
    }

    // p = Wph @ h + bp; softmax
    rnn_gemm<<<grid, THREADS, SMEM_BYTES>>>(wph, ph, maxbits + 2, nullptr,
                                            nullptr, bp, p, nullptr, 1);
    softmax_kernel<<<MDIM / 8, 256>>>(p, (float*)d_out);
}

// round 14
// speedup vs baseline: 1.6109x; 1.0702x over previous
#include <cuda_runtime.h>
#include <math.h>
#include <stdint.h>

// ---------------------------------------------------------------- dims
constexpr int MDIM = 2048, KDIM = 2048, NDIM = 256;

// ---------------------------------------------------------------- tiling
constexpr int BM = 64, BN = 64;
constexpr int THREADS = 512;                 // 16 warps: 4 (m) x 4 (n)
constexpr int NWARP = THREADS / 32;
constexpr int STAGES = 5;                    // k128 super-stages
constexpr int PREF = 4;
constexpr int NIT = KDIM / 128;              // 16
// packed swizzled tile: 64 rows x 64 B = 4096 B
constexpr int TILE_B = 4096;
constexpr int KT_B   = 2 * TILE_B;           // digit1|digit2 per k64 = 8192
constexpr int BLK_B  = 32 * KT_B;            // per 64-row block = 262144
constexpr int STAGE_BYTES = 4 * KT_B;        // A(k128) + B(k128) = 32768
constexpr int SM_STAGE0 = 1024;
constexpr int SMEM_BYTES = SM_STAGE0 + STAGES * STAGE_BYTES;   // 164864

// blobs: [blk64][k64][digit1 4K | digit2 4K]
constexpr size_t WBLOB = 32ull * BLK_B;      // 8 MB per weight
constexpr size_t HBLOB = 4ull * BLK_B;       // 1 MB per h/x

// ---------------------------------------------------------------- scratch
__device__ __align__(128) int8_t g_Whx[WBLOB];
__device__ __align__(128) int8_t g_Whh[WBLOB];
__device__ __align__(128) int8_t g_Wph[WBLOB];
__device__ __align__(128) int8_t g_x [HBLOB];
__device__ __align__(128) int8_t g_h0[HBLOB];
__device__ __align__(128) int8_t g_h1[HBLOB];
__device__ float g_c[MDIM * NDIM];
__device__ float g_p[MDIM * NDIM];
__device__ int   g_maxbits[4];

// swizzled byte offset within a packed tile: logical (row, col) 64x64
__device__ __forceinline__ uint32_t tswz(int row, int col) {
    return (uint32_t)(row * 64 + (((col & 48) ^ (((row >> 1) & 3) << 4)) |
                                  (col & 15)));
}

// ---------------------------------------------------------------- helpers
__device__ __forceinline__ uint32_t smem_u32(const void* p) {
    uint32_t a;
    asm("{ .reg .u64 t; cvta.to.shared.u64 t, %1; cvt.u32.u64 %0, t; }"
        : "=r"(a) : "l"(p));
    return a;
}

__device__ __forceinline__ void mma_s8(int* c, const uint32_t* a,
                                       const uint32_t* b) {
    asm volatile(
        "mma.sync.aligned.m16n8k32.row.col.s32.s8.s8.s32 "
        "{%0,%1,%2,%3}, {%4,%5,%6,%7}, {%8,%9}, {%0,%1,%2,%3};"
        : "+r"(c[0]), "+r"(c[1]), "+r"(c[2]), "+r"(c[3])
        : "r"(a[0]), "r"(a[1]), "r"(a[2]), "r"(a[3]), "r"(b[0]), "r"(b[1]));
}

__device__ __forceinline__ void ldsm_x4(uint32_t* r, uint32_t addr) {
    asm volatile("ldmatrix.sync.aligned.m8n8.x4.shared.b16 {%0,%1,%2,%3}, [%4];"
                 : "=r"(r[0]), "=r"(r[1]), "=r"(r[2]), "=r"(r[3]) : "r"(addr));
}

__device__ __forceinline__ void bulkcp(uint32_t sdst, const void* gsrc,
                                       uint32_t bytes, uint32_t mbar) {
    asm volatile(
        "cp.async.bulk.shared::cta.global.mbarrier::complete_tx::bytes "
        "[%0], [%1], %2, [%3];"
        :: "r"(sdst), "l"(gsrc), "r"(bytes), "r"(mbar) : "memory");
}

__device__ __forceinline__ void mbar_init(uint32_t mbar, uint32_t cnt) {
    asm volatile("mbarrier.init.shared.b64 [%0], %1;"
                 :: "r"(mbar), "r"(cnt) : "memory");
}

__device__ __forceinline__ void mbar_expect_tx(uint32_t mbar, uint32_t bytes) {
    asm volatile("mbarrier.arrive.expect_tx.shared.b64 _, [%0], %1;"
                 :: "r"(mbar), "r"(bytes) : "memory");
}

__device__ __forceinline__ void mbar_arrive(uint32_t mbar) {
    asm volatile("mbarrier.arrive.shared.b64 _, [%0];"
                 :: "r"(mbar) : "memory");
}

__device__ __forceinline__ void mbar_wait(uint32_t mb, uint32_t parity) {
    asm volatile(
        "{\n\t.reg .pred P;\n\t"
        "L0_%=:\n\t"
        "mbarrier.try_wait.parity.acquire.cta.shared::cta.b64 P, [%0], %1, 0x989680;\n\t"
        "@P bra.uni L1_%=;\n\t"
        "bra.uni L0_%=;\n\t"
        "L1_%=:\n\t}"
        :: "r"(mb), "r"(parity) : "memory");
}

__device__ __forceinline__ void mbar_wait_relaxed(uint32_t mb, uint32_t parity) {
    asm volatile(
        "{\n\t.reg .pred P;\n\t"
        "L0_%=:\n\t"
        "mbarrier.try_wait.parity.relaxed.cta.shared::cta.b64 P, [%0], %1, 0x989680;\n\t"
        "@P bra.uni L1_%=;\n\t"
        "bra.uni L0_%=;\n\t"
        "L1_%=:\n\t}"
        :: "r"(mb), "r"(parity) : "memory");
}

__device__ __forceinline__ void quant2(float q, int8_t& d1, int8_t& d2) {
    float b1 = rintf(q);
    float b2 = rintf((q - b1) * 256.0f);
    b2 = fminf(fmaxf(b2, -127.0f), 127.0f);
    d1 = (int8_t)(int)b1;
    d2 = (int8_t)(int)b2;
}

// ---------------------------------------------------------------- prep
__global__ void reset_kernel() {
    if (threadIdx.x < 4) g_maxbits[threadIdx.x] = 0;
}

__global__ void maxabs_kernel(const float* __restrict__ w0,
                              const float* __restrict__ w1,
                              const float* __restrict__ w2,
                              const float* __restrict__ x) {
    const int t = blockIdx.y;
    const float* src = (t == 0) ? w0 : (t == 1) ? w1 : (t == 2) ? w2 : x;
    const int len = (t == 3) ? KDIM * NDIM : MDIM * KDIM;
    float m = 0.0f;
    for (int i = blockIdx.x * 256 + threadIdx.x; i < len; i += 2048 * 256)
        m = fmaxf(m, fabsf(src[i]));
    #pragma unroll
    for (int o = 16; o > 0; o >>= 1)
        m = fmaxf(m, __shfl_xor_sync(~0u, m, o));
    if ((threadIdx.x & 31) == 0)
        atomicMax(&g_maxbits[t], __float_as_int(m));
}

__global__ void quant_kernel(const float* __restrict__ w0,
                             const float* __restrict__ w1,
                             const float* __restrict__ w2,
                             const float* __restrict__ x) {
    const int t = blockIdx.y;
    const int len = (t == 3) ? KDIM * NDIM : MDIM * KDIM;
    const int i = blockIdx.x * 256 + threadIdx.x;
    if (i >= len) return;
    const float mx = fmaxf(__int_as_float(g_maxbits[t]), 1e-20f);
    const float iq = 127.0f / mx;
    int8_t d1, d2;
    if (t == 3) {
        const int k = i / NDIM, n = i % NDIM;
        quant2(x[i] * iq, d1, d2);
        const size_t off = (size_t)(n >> 6) * BLK_B + (size_t)(k >> 6) * KT_B +
                           tswz(n & 63, k & 63);
        g_x[off] = d1;
        g_x[off + TILE_B] = d2;
    } else {
        const int m = i >> 11, k = i & 2047;
        const float* w = (t == 0) ? w0 : (t == 1) ? w1 : w2;
        int8_t* o = (t == 0) ? g_Whx : (t == 1) ? g_Whh : g_Wph;
        quant2(w[i] * iq, d1, d2);
        const size_t off = (size_t)(m >> 6) * BLK_B + (size_t)(k >> 6) * KT_B +
                           tswz(m & 63, k & 63);
        o[off] = d1;
        o[off + TILE_B] = d2;
    }
}

// step 1 (h0 = 0): h1 = tanh(c + bh) -> h blob (row=n, col=m)
__global__ void first_step_kernel(const float* __restrict__ c,
                                  const float* __restrict__ bh,
                                  int8_t* __restrict__ outH) {
    const int i = blockIdx.x * 256 + threadIdx.x;
    if (i >= MDIM * NDIM) return;
    const int n = i >> 11, m = i & 2047;
    const float v = tanhf(c[(size_t)m * NDIM + n] + bh[n]);
    int8_t d1, d2;
    quant2(v * 127.0f, d1, d2);
    const size_t off = (size_t)(n >> 6) * BLK_B + (size_t)(m >> 6) * KT_B +
                       tswz(n & 63, m & 63);
    outH[off] = d1;
    outH[off + TILE_B] = d2;
}

// ---------------------------------------------------------------- main GEMM
// D = sA*sB*(A1@B1 + (A1@B2 + A2@B1)/256); blobs [blk][k64][d1|d2] swizzled.
// mode 0: outF = D     mode 1: outF = D + bias
// mode 2: v = tanh(D + addc + bias); quant2(v*127) -> outH blob
// Pipeline: per-stage full (TMA tx) + empty (16 warp arrivals) mbarriers.
// NO per-iteration __syncthreads — warps run decoupled.
__global__ void __launch_bounds__(THREADS) rnn_gemm(
    const int8_t* __restrict__ A, const int8_t* __restrict__ B,
    const int* __restrict__ maxA, const int* __restrict__ maxB,
    const float* __restrict__ addc, const float* __restrict__ bias,
    float* __restrict__ outF, int8_t* __restrict__ outH, int mode)
{
    extern __shared__ __align__(16) char sm[];
    const uint32_t sbase = smem_u32(sm);
    const int tid  = threadIdx.x;
    const int lane = tid & 31;
    const int wid  = tid >> 5;
    const int wm0  = (wid & 3) * 16;     // 4 warps in m
    const int wn0  = (wid >> 2) * 16;    // 4 warps in n
    const int mblk = blockIdx.y;         // 0..31
    const int nblk = blockIdx.x;         // 0..3
    const int m0   = mblk * BM;
    const int n0   = nblk * BN;

    // mbar layout: full[s] = sbase + s*16, empty[s] = sbase + s*16 + 8
    auto fullb  = [&](int s) { return sbase + (uint32_t)s * 16; };
    auto emptyb = [&](int s) { return sbase + (uint32_t)s * 16 + 8; };

    const float sa  = __int_as_float(*maxA) * (1.0f / 127.0f);
    const float sb  = maxB ? __int_as_float(*maxB) * (1.0f / 127.0f)
                           : (1.0f / 127.0f);
    const float sAB = sa * sb;

    int C1[2][4] = {};
    int C2[2][4] = {};

    // per-lane ldsm address pieces (packed swizzled tiles)
    const uint32_t arow = (uint32_t)((wm0 + (lane & 15)) * 64);
    const uint32_t achk = (uint32_t)((lane >> 4) * 16);
    const uint32_t aswz = (uint32_t)((((lane & 15) >> 1) & 3) << 4);
    const uint32_t brow = (uint32_t)((wn0 + (lane & 7) + ((lane >> 4) & 1) * 8) * 64);
    const uint32_t bchk = (uint32_t)(((lane >> 3) & 1) * 16);
    const uint32_t bswz = (uint32_t)(((((lane & 7) + ((lane >> 4) & 1) * 8) >> 1) & 3) << 4);

    if (tid == 0) {
        #pragma unroll
        for (int s = 0; s < STAGES; ++s) {
            mbar_init(fullb(s), 1);
            mbar_init(emptyb(s), NWARP);
        }
        asm volatile("fence.proxy.async.shared::cta;" ::: "memory");
    }
    __syncthreads();

    auto issue_stage = [&](int j) {
        const int s = j % STAGES;
        if (j >= STAGES)   // wait for all warps to release the slot
            mbar_wait_relaxed(emptyb(s), (uint32_t)((j / STAGES - 1) & 1));
        const uint32_t dst = sbase + SM_STAGE0 + s * STAGE_BYTES;
        mbar_expect_tx(fullb(s), STAGE_BYTES);
        bulkcp(dst, A + (size_t)mblk * BLK_B + (size_t)(2 * j) * KT_B,
               2 * KT_B, fullb(s));
        bulkcp(dst + 2 * KT_B, B + (size_t)nblk * BLK_B + (size_t)(2 * j) * KT_B,
               2 * KT_B, fullb(s));
    };

    if (tid == 0) {
        #pragma unroll
        for (int s = 0; s < PREF; ++s) issue_stage(s);
    }

    for (int it = 0; it < NIT; ++it) {
        if (tid == 0 && it + PREF < NIT) issue_stage(it + PREF);

        const int s = it % STAGES;
        mbar_wait(fullb(s), (uint32_t)((it / STAGES) & 1));

        const uint32_t st = sbase + SM_STAGE0 + s * STAGE_BYTES;
        #pragma unroll
        for (int h = 0; h < 2; ++h) {
            const uint32_t sA1 = st + h * KT_B;
            const uint32_t sA2 = sA1 + TILE_B;
            const uint32_t sB1 = st + 2 * KT_B + h * KT_B;
            const uint32_t sB2 = sB1 + TILE_B;
            #pragma unroll
            for (int kk = 0; kk < 2; ++kk) {
                const uint32_t ka = ((kk * 32) | achk) ^ aswz;
                const uint32_t kb2 = ((kk * 32) | bchk) ^ bswz;
                uint32_t a1f[4], a2f[4], b1f[4], b2f[4];
                ldsm_x4(a1f, sA1 + arow + ka);
                ldsm_x4(a2f, sA2 + arow + ka);
                ldsm_x4(b1f, sB1 + brow + kb2);
                ldsm_x4(b2f, sB2 + brow + kb2);
                #pragma unroll
                for (int nt = 0; nt < 2; ++nt) {
                    mma_s8(C1[nt], a1f, &b1f[nt * 2]);
                    mma_s8(C2[nt], a1f, &b2f[nt * 2]);
                    mma_s8(C2[nt], a2f, &b1f[nt * 2]);
                }
            }
        }
        // this warp is done reading stage s — release it
        if (lane == 0) mbar_arrive(emptyb(s));
    }

    // ------------------------------------------------------------ epilogue
    if (mode == 2) {
        __syncthreads();   // all warps past the loop; stages free for reuse
        int8_t* stg = (int8_t*)sm + SM_STAGE0;
        #pragma unroll
        for (int nt = 0; nt < 2; ++nt) {
            const int lr = wm0 + (lane >> 2);             // m local
            const int lc = wn0 + nt * 8 + 2 * (lane & 3); // n local
            const int gm = m0 + lr, gn = n0 + lc;
            float2 c0 = *(const float2*)(addc + (size_t)gm * NDIM + gn);
            float2 c1 = *(const float2*)(addc + (size_t)(gm + 8) * NDIM + gn);
            float2 bv = *(const float2*)(bias + gn);
            float vv[4];
            vv[0] = tanhf(sAB * ((float)C1[nt][0] + (float)C2[nt][0] * (1.0f / 256.0f)) + c0.x + bv.x) * 127.0f;
            vv[1] = tanhf(sAB * ((float)C1[nt][1] + (float)C2[nt][1] * (1.0f / 256.0f)) + c0.y + bv.y) * 127.0f;
            vv[2] = tanhf(sAB * ((float)C1[nt][2] + (float)C2[nt][2] * (1.0f / 256.0f)) + c1.x + bv.x) * 127.0f;
            vv[3] = tanhf(sAB * ((float)C1[nt][3] + (float)C2[nt][3] * (1.0f / 256.0f)) + c1.y + bv.y) * 127.0f;
            #pragma unroll
            for (int q = 0; q < 4; ++q) {
                const int r = lr + (q >> 1) * 8;      // m local (blob col)
                const int cc = lc + (q & 1);          // n local (blob row)
                int8_t d1, d2;
                quant2(vv[q], d1, d2);
                const uint32_t o = tswz(cc, r);
                stg[o] = d1;
                stg[o + TILE_B] = d2;
            }
        }
        __syncthreads();
        int8_t* dstb = outH + (size_t)nblk * BLK_B + (size_t)mblk * KT_B;
        *(uint4*)&dstb[tid * 16] = *(const uint4*)&stg[tid * 16];
    } else {
        #pragma unroll
        for (int nt = 0; nt < 2; ++nt) {
            const int lr = wm0 + (lane >> 2);
            const int lc = wn0 + nt * 8 + 2 * (lane & 3);
            const int gm = m0 + lr, gn = n0 + lc;
            float bx = 0.f, by = 0.f;
            if (mode == 1) {
                float2 bv = *(const float2*)(bias + gn);
                bx = bv.x; by = bv.y;
            }
            float2 o0, o1;
            o0.x = sAB * ((float)C1[nt][0] + (float)C2[nt][0] * (1.0f / 256.0f)) + bx;
            o0.y = sAB * ((float)C1[nt][1] + (float)C2[nt][1] * (1.0f / 256.0f)) + by;
            o1.x = sAB * ((float)C1[nt][2] + (float)C2[nt][2] * (1.0f / 256.0f)) + bx;
            o1.y = sAB * ((float)C1[nt][3] + (float)C2[nt][3] * (1.0f / 256.0f)) + by;
            *(float2*)(outF + (size_t)gm * NDIM + gn) = o0;
            *(float2*)(outF + (size_t)(gm + 8) * NDIM + gn) = o1;
        }
    }
}

// ---------------------------------------------------------------- softmax
__global__ __launch_bounds__(256) void softmax_kernel(
    const float* __restrict__ p, float* __restrict__ out)
{
    const int row  = blockIdx.x * 8 + (threadIdx.x >> 5);
    const int lane = threadIdx.x & 31;
    const float* pr = p + (size_t)row * NDIM;
    float v[8];
    float mx = -INFINITY;
    #pragma unroll
    for (int i = 0; i < 8; ++i) { v[i] = pr[lane + 32 * i]; mx = fmaxf(mx, v[i]); }
    #pragma unroll
    for (int o = 16; o > 0; o >>= 1) mx = fmaxf(mx, __shfl_xor_sync(~0u, mx, o));
    float s = 0.f;
    #pragma unroll
    for (int i = 0; i < 8; ++i) { v[i] = expf(v[i] - mx); s += v[i]; }
    #pragma unroll
    for (int o = 16; o > 0; o >>= 1) s += __shfl_xor_sync(~0u, s, o);
    const float inv = 1.0f / s;
    float* orow = out + (size_t)row * NDIM;
    #pragma unroll
    for (int i = 0; i < 8; ++i) orow[lane + 32 * i] = v[i] * inv;
}

// ---------------------------------------------------------------- launch
extern "C" void kernel_launch(void* const* d_in, const int* in_sizes, int n_in,
                              void* d_out, int out_size)
{
    const float* x   = (const float*)d_in[0];
    const float* Whx = (const float*)d_in[1];
    const float* Whh = (const float*)d_in[2];
    const float* Wph = (const float*)d_in[3];
    const float* bh  = (const float*)d_in[4];
    const float* bp  = (const float*)d_in[5];

    int8_t *whx, *whh, *wph, *xb, *h0, *h1;
    float *c, *p;
    int* maxbits;
    cudaGetSymbolAddress((void**)&whx, g_Whx);
    cudaGetSymbolAddress((void**)&whh, g_Whh);
    cudaGetSymbolAddress((void**)&wph, g_Wph);
    cudaGetSymbolAddress((void**)&xb,  g_x);
    cudaGetSymbolAddress((void**)&h0,  g_h0);
    cudaGetSymbolAddress((void**)&h1,  g_h1);
    cudaGetSymbolAddress((void**)&c,   g_c);
    cudaGetSymbolAddress((void**)&p,   g_p);
    cudaGetSymbolAddress((void**)&maxbits, g_maxbits);

    cudaFuncSetAttribute(rnn_gemm, cudaFuncAttributeMaxDynamicSharedMemorySize,
                         SMEM_BYTES);

    reset_kernel<<<1, 32>>>();
    maxabs_kernel<<<dim3(2048, 4), 256>>>(Whx, Whh, Wph, x);
    quant_kernel<<<dim3((MDIM * KDIM + 255) / 256, 4), 256>>>(Whx, Whh, Wph, x);

    const dim3 grid(NDIM / BN, MDIM / BM);   // (4, 32) = 128 CTAs

    // c = Whx @ x
    rnn_gemm<<<grid, THREADS, SMEM_BYTES>>>(whx, xb, maxbits + 0, maxbits + 3,
                                            nullptr, nullptr, c, nullptr, 0);

    // step 1: h1 = tanh(c + bh) (h0 = 0)
    first_step_kernel<<<(MDIM * NDIM + 255) / 256, 256>>>(c, bh, h0);

    // steps 2..256
    int8_t *ph = h0, *pn = h1;
    for (int t = 1; t < NDIM; ++t) {
        rnn_gemm<<<grid, THREADS, SMEM_BYTES>>>(whh, ph, maxbits + 1, nullptr,
                                                c, bh, nullptr, pn, 2);
        int8_t* tm = ph; ph = pn; pn = tm;
    }

    // p = Wph @ h + bp; softmax
    rnn_gemm<<<grid, THREADS, SMEM_BYTES>>>(wph, ph, maxbits + 2, nullptr,
                                            nullptr, bp, p, nullptr, 1);
    softmax_kernel<<<MDIM / 8, 256>>>(p, (float*)d_out);
}

// round 15
// speedup vs baseline: 1.7276x; 1.0724x over previous
#include <cuda_runtime.h>
#include <math.h>
#include <stdint.h>

// ---------------------------------------------------------------- dims
constexpr int MDIM = 2048, KDIM = 2048, NDIM = 256;

// ---------------------------------------------------------------- tiling
constexpr int BM = 64, BN = 64;
constexpr int THREADS = 512;                 // 16 warps: 4 (m) x 4 (n)
constexpr int NWARP = THREADS / 32;
constexpr int STAGES = 5;                    // k128 super-stages
constexpr int PREF = 4;
constexpr int NIT = KDIM / 128;              // 16
constexpr int NSTEPS = 255;                  // recurrence steps 2..256
// packed swizzled tile: 64 rows x 64 B = 4096 B
constexpr int TILE_B = 4096;
constexpr int KT_B   = 2 * TILE_B;           // digit1|digit2 per k64 = 8192
constexpr int BLK_B  = 32 * KT_B;            // per 64-row block = 262144
constexpr int STAGE_BYTES = 4 * KT_B;        // A(k128) + B(k128) = 32768
constexpr int SM_STAGE0 = 1024;
constexpr int SM_STG = SM_STAGE0 + STAGES * STAGE_BYTES;       // epi staging
constexpr int SMEM_BYTES = SM_STG + 2 * TILE_B;                // 173056

// blobs: [blk64][k64][digit1 4K | digit2 4K]
constexpr size_t WBLOB = 32ull * BLK_B;
constexpr size_t HBLOB = 4ull * BLK_B;

// ---------------------------------------------------------------- scratch
__device__ __align__(128) int8_t g_Whx[WBLOB];
__device__ __align__(128) int8_t g_Whh[WBLOB];
__device__ __align__(128) int8_t g_Wph[WBLOB];
__device__ __align__(128) int8_t g_x [HBLOB];
__device__ __align__(128) int8_t g_h0[HBLOB];
__device__ __align__(128) int8_t g_h1[HBLOB];
__device__ float g_c[MDIM * NDIM];
__device__ float g_p[MDIM * NDIM];
__device__ int   g_maxbits[4];
__device__ unsigned g_bar;                   // persistent-kernel step barrier

// swizzled byte offset within a packed tile: logical (row, col) 64x64
__device__ __forceinline__ uint32_t tswz(int row, int col) {
    return (uint32_t)(row * 64 + (((col & 48) ^ (((row >> 1) & 3) << 4)) |
                                  (col & 15)));
}

// ---------------------------------------------------------------- helpers
__device__ __forceinline__ uint32_t smem_u32(const void* p) {
    uint32_t a;
    asm("{ .reg .u64 t; cvta.to.shared.u64 t, %1; cvt.u32.u64 %0, t; }"
        : "=r"(a) : "l"(p));
    return a;
}

__device__ __forceinline__ void mma_s8(int* c, const uint32_t* a,
                                       const uint32_t* b) {
    asm volatile(
        "mma.sync.aligned.m16n8k32.row.col.s32.s8.s8.s32 "
        "{%0,%1,%2,%3}, {%4,%5,%6,%7}, {%8,%9}, {%0,%1,%2,%3};"
        : "+r"(c[0]), "+r"(c[1]), "+r"(c[2]), "+r"(c[3])
        : "r"(a[0]), "r"(a[1]), "r"(a[2]), "r"(a[3]), "r"(b[0]), "r"(b[1]));
}

__device__ __forceinline__ void ldsm_x4(uint32_t* r, uint32_t addr) {
    asm volatile("ldmatrix.sync.aligned.m8n8.x4.shared.b16 {%0,%1,%2,%3}, [%4];"
                 : "=r"(r[0]), "=r"(r[1]), "=r"(r[2]), "=r"(r[3]) : "r"(addr));
}

__device__ __forceinline__ void bulkcp(uint32_t sdst, const void* gsrc,
                                       uint32_t bytes, uint32_t mbar) {
    asm volatile(
        "cp.async.bulk.shared::cta.global.mbarrier::complete_tx::bytes "
        "[%0], [%1], %2, [%3];"
        :: "r"(sdst), "l"(gsrc), "r"(bytes), "r"(mbar) : "memory");
}

__device__ __forceinline__ void mbar_init(uint32_t mbar, uint32_t cnt) {
    asm volatile("mbarrier.init.shared.b64 [%0], %1;"
                 :: "r"(mbar), "r"(cnt) : "memory");
}

__device__ __forceinline__ void mbar_expect_tx(uint32_t mbar, uint32_t bytes) {
    asm volatile("mbarrier.arrive.expect_tx.shared.b64 _, [%0], %1;"
                 :: "r"(mbar), "r"(bytes) : "memory");
}

__device__ __forceinline__ void mbar_arrive(uint32_t mbar) {
    asm volatile("mbarrier.arrive.shared.b64 _, [%0];"
                 :: "r"(mbar) : "memory");
}

__device__ __forceinline__ void mbar_wait(uint32_t mb, uint32_t parity) {
    asm volatile(
        "{\n\t.reg .pred P;\n\t"
        "L0_%=:\n\t"
        "mbarrier.try_wait.parity.acquire.cta.shared::cta.b64 P, [%0], %1, 0x989680;\n\t"
        "@P bra.uni L1_%=;\n\t"
        "bra.uni L0_%=;\n\t"
        "L1_%=:\n\t}"
        :: "r"(mb), "r"(parity) : "memory");
}

__device__ __forceinline__ void mbar_wait_relaxed(uint32_t mb, uint32_t parity) {
    asm volatile(
        "{\n\t.reg .pred P;\n\t"
        "L0_%=:\n\t"
        "mbarrier.try_wait.parity.relaxed.cta.shared::cta.b64 P, [%0], %1, 0x989680;\n\t"
        "@P bra.uni L1_%=;\n\t"
        "bra.uni L0_%=;\n\t"
        "L1_%=:\n\t}"
        :: "r"(mb), "r"(parity) : "memory");
}

__device__ __forceinline__ void quant2(float q, int8_t& d1, int8_t& d2) {
    float b1 = rintf(q);
    float b2 = rintf((q - b1) * 256.0f);
    b2 = fminf(fmaxf(b2, -127.0f), 127.0f);
    d1 = (int8_t)(int)b1;
    d2 = (int8_t)(int)b2;
}

// ---------------------------------------------------------------- prep
__global__ void reset_kernel() {
    if (threadIdx.x < 4) g_maxbits[threadIdx.x] = 0;
    if (threadIdx.x == 4) g_bar = 0u;
}

__global__ void maxabs_kernel(const float* __restrict__ w0,
                              const float* __restrict__ w1,
                              const float* __restrict__ w2,
                              const float* __restrict__ x) {
    const int t = blockIdx.y;
    const float* src = (t == 0) ? w0 : (t == 1) ? w1 : (t == 2) ? w2 : x;
    const int len = (t == 3) ? KDIM * NDIM : MDIM * KDIM;
    float m = 0.0f;
    for (int i = blockIdx.x * 256 + threadIdx.x; i < len; i += 2048 * 256)
        m = fmaxf(m, fabsf(src[i]));
    #pragma unroll
    for (int o = 16; o > 0; o >>= 1)
        m = fmaxf(m, __shfl_xor_sync(~0u, m, o));
    if ((threadIdx.x & 31) == 0)
        atomicMax(&g_maxbits[t], __float_as_int(m));
}

__global__ void quant_kernel(const float* __restrict__ w0,
                             const float* __restrict__ w1,
                             const float* __restrict__ w2,
                             const float* __restrict__ x) {
    const int t = blockIdx.y;
    const int len = (t == 3) ? KDIM * NDIM : MDIM * KDIM;
    const int i = blockIdx.x * 256 + threadIdx.x;
    if (i >= len) return;
    const float mx = fmaxf(__int_as_float(g_maxbits[t]), 1e-20f);
    const float iq = 127.0f / mx;
    int8_t d1, d2;
    if (t == 3) {
        const int k = i / NDIM, n = i % NDIM;
        quant2(x[i] * iq, d1, d2);
        const size_t off = (size_t)(n >> 6) * BLK_B + (size_t)(k >> 6) * KT_B +
                           tswz(n & 63, k & 63);
        g_x[off] = d1;
        g_x[off + TILE_B] = d2;
    } else {
        const int m = i >> 11, k = i & 2047;
        const float* w = (t == 0) ? w0 : (t == 1) ? w1 : w2;
        int8_t* o = (t == 0) ? g_Whx : (t == 1) ? g_Whh : g_Wph;
        quant2(w[i] * iq, d1, d2);
        const size_t off = (size_t)(m >> 6) * BLK_B + (size_t)(k >> 6) * KT_B +
                           tswz(m & 63, k & 63);
        o[off] = d1;
        o[off + TILE_B] = d2;
    }
}

__global__ void first_step_kernel(const float* __restrict__ c,
                                  const float* __restrict__ bh,
                                  int8_t* __restrict__ outH) {
    const int i = blockIdx.x * 256 + threadIdx.x;
    if (i >= MDIM * NDIM) return;
    const int n = i >> 11, m = i & 2047;
    const float v = tanhf(c[(size_t)m * NDIM + n] + bh[n]);
    int8_t d1, d2;
    quant2(v * 127.0f, d1, d2);
    const size_t off = (size_t)(n >> 6) * BLK_B + (size_t)(m >> 6) * KT_B +
                       tswz(n & 63, m & 63);
    outH[off] = d1;
    outH[off + TILE_B] = d2;
}

// ---------------------------------------------------------------- single GEMM
// (used for c = Whx@x and p = Wph@h; modes 0/1 only)
__global__ void __launch_bounds__(THREADS) rnn_gemm(
    const int8_t* __restrict__ A, const int8_t* __restrict__ B,
    const int* __restrict__ maxA, const int* __restrict__ maxB,
    const float* __restrict__ bias, float* __restrict__ outF, int mode)
{
    extern __shared__ __align__(16) char sm[];
    const uint32_t sbase = smem_u32(sm);
    const int tid  = threadIdx.x;
    const int lane = tid & 31;
    const int wid  = tid >> 5;
    const int wm0  = (wid & 3) * 16;
    const int wn0  = (wid >> 2) * 16;
    const int mblk = blockIdx.y;
    const int nblk = blockIdx.x;
    const int m0   = mblk * BM;
    const int n0   = nblk * BN;

    auto fullb  = [&](int s) { return sbase + (uint32_t)s * 16; };
    auto emptyb = [&](int s) { return sbase + (uint32_t)s * 16 + 8; };

    const float sa  = __int_as_float(*maxA) * (1.0f / 127.0f);
    const float sb  = maxB ? __int_as_float(*maxB) * (1.0f / 127.0f)
                           : (1.0f / 127.0f);
    const float sAB = sa * sb;

    int C1[2][4] = {};
    int C2[2][4] = {};

    const uint32_t arow = (uint32_t)((wm0 + (lane & 15)) * 64);
    const uint32_t achk = (uint32_t)((lane >> 4) * 16);
    const uint32_t aswz = (uint32_t)((((lane & 15) >> 1) & 3) << 4);
    const uint32_t brow = (uint32_t)((wn0 + (lane & 7) + ((lane >> 4) & 1) * 8) * 64);
    const uint32_t bchk = (uint32_t)(((lane >> 3) & 1) * 16);
    const uint32_t bswz = (uint32_t)(((((lane & 7) + ((lane >> 4) & 1) * 8) >> 1) & 3) << 4);

    if (tid == 0) {
        #pragma unroll
        for (int s = 0; s < STAGES; ++s) {
            mbar_init(fullb(s), 1);
            mbar_init(emptyb(s), NWARP);
        }
        asm volatile("fence.proxy.async.shared::cta;" ::: "memory");
    }
    __syncthreads();

    auto issue_stage = [&](int j) {
        const int s = j % STAGES;
        if (j >= STAGES)
            mbar_wait_relaxed(emptyb(s), (uint32_t)((j / STAGES - 1) & 1));
        const uint32_t dst = sbase + SM_STAGE0 + s * STAGE_BYTES;
        mbar_expect_tx(fullb(s), STAGE_BYTES);
        bulkcp(dst, A + (size_t)mblk * BLK_B + (size_t)(2 * j) * KT_B,
               2 * KT_B, fullb(s));
        bulkcp(dst + 2 * KT_B, B + (size_t)nblk * BLK_B + (size_t)(2 * j) * KT_B,
               2 * KT_B, fullb(s));
    };

    if (tid == 0) {
        #pragma unroll
        for (int s = 0; s < PREF; ++s) issue_stage(s);
    }

    for (int it = 0; it < NIT; ++it) {
        if (tid == 0 && it + PREF < NIT) issue_stage(it + PREF);
        const int s = it % STAGES;
        mbar_wait(fullb(s), (uint32_t)((it / STAGES) & 1));
        const uint32_t st = sbase + SM_STAGE0 + s * STAGE_BYTES;
        #pragma unroll
        for (int h = 0; h < 2; ++h) {
            const uint32_t sA1 = st + h * KT_B;
            const uint32_t sB1 = st + 2 * KT_B + h * KT_B;
            #pragma unroll
            for (int kk = 0; kk < 2; ++kk) {
                const uint32_t ka = ((kk * 32) | achk) ^ aswz;
                const uint32_t kb2 = ((kk * 32) | bchk) ^ bswz;
                uint32_t a1f[4], a2f[4], b1f[4], b2f[4];
                ldsm_x4(a1f, sA1 + arow + ka);
                ldsm_x4(a2f, sA1 + TILE_B + arow + ka);
                ldsm_x4(b1f, sB1 + brow + kb2);
                ldsm_x4(b2f, sB1 + TILE_B + brow + kb2);
                #pragma unroll
                for (int nt = 0; nt < 2; ++nt) {
                    mma_s8(C1[nt], a1f, &b1f[nt * 2]);
                    mma_s8(C2[nt], a1f, &b2f[nt * 2]);
                    mma_s8(C2[nt], a2f, &b1f[nt * 2]);
                }
            }
        }
        if (lane == 0) mbar_arrive(emptyb(s));
    }

    #pragma unroll
    for (int nt = 0; nt < 2; ++nt) {
        const int lr = wm0 + (lane >> 2);
        const int lc = wn0 + nt * 8 + 2 * (lane & 3);
        const int gm = m0 + lr, gn = n0 + lc;
        float bx = 0.f, by = 0.f;
        if (mode == 1) {
            float2 bv = *(const float2*)(bias + gn);
            bx = bv.x; by = bv.y;
        }
        float2 o0, o1;
        o0.x = sAB * ((float)C1[nt][0] + (float)C2[nt][0] * (1.0f / 256.0f)) + bx;
        o0.y = sAB * ((float)C1[nt][1] + (float)C2[nt][1] * (1.0f / 256.0f)) + by;
        o1.x = sAB * ((float)C1[nt][2] + (float)C2[nt][2] * (1.0f / 256.0f)) + bx;
        o1.y = sAB * ((float)C1[nt][3] + (float)C2[nt][3] * (1.0f / 256.0f)) + by;
        *(float2*)(outF + (size_t)gm * NDIM + gn) = o0;
        *(float2*)(outF + (size_t)(gm + 8) * NDIM + gn) = o1;
    }
}

// ---------------------------------------------------------------- persistent
// All 255 recurrence steps in one kernel. 128 CTAs (1/SM, co-resident).
// Step t: reads h[t&1] blob, writes h[(t+1)&1] blob. Global counter barrier.
__global__ void __launch_bounds__(THREADS) rnn_steps(
    const int8_t* __restrict__ A,            // Whh blob
    int8_t* __restrict__ hb0, int8_t* __restrict__ hb1,
    const int* __restrict__ maxA,
    const float* __restrict__ addc, const float* __restrict__ bias)
{
    extern __shared__ __align__(16) char sm[];
    const uint32_t sbase = smem_u32(sm);
    const int tid  = threadIdx.x;
    const int lane = tid & 31;
    const int wid  = tid >> 5;
    const int wm0  = (wid & 3) * 16;
    const int wn0  = (wid >> 2) * 16;
    const int mblk = blockIdx.y;
    const int nblk = blockIdx.x;
    const int m0   = mblk * BM;
    const int n0   = nblk * BN;

    // mbars: fullA[s]=s*24, fullB[s]=s*24+8, empty[s]=s*24+16
    auto fullA  = [&](int s) { return sbase + (uint32_t)s * 24; };
    auto fullB  = [&](int s) { return sbase + (uint32_t)s * 24 + 8; };
    auto emptyb = [&](int s) { return sbase + (uint32_t)s * 24 + 16; };

    const float sa  = __int_as_float(*maxA) * (1.0f / 127.0f);
    const float sAB = sa * (1.0f / 127.0f);

    const uint32_t arow = (uint32_t)((wm0 + (lane & 15)) * 64);
    const uint32_t achk = (uint32_t)((lane >> 4) * 16);
    const uint32_t aswz = (uint32_t)((((lane & 15) >> 1) & 3) << 4);
    const uint32_t brow = (uint32_t)((wn0 + (lane & 7) + ((lane >> 4) & 1) * 8) * 64);
    const uint32_t bchk = (uint32_t)(((lane >> 3) & 1) * 16);
    const uint32_t bswz = (uint32_t)(((((lane & 7) + ((lane >> 4) & 1) * 8) >> 1) & 3) << 4);

    // hoist c + bh per output element (constant across steps)
    float cb[2][4];
    #pragma unroll
    for (int nt = 0; nt < 2; ++nt) {
        const int gm = m0 + wm0 + (lane >> 2);
        const int gn = n0 + wn0 + nt * 8 + 2 * (lane & 3);
        float2 c0 = *(const float2*)(addc + (size_t)gm * NDIM + gn);
        float2 c1 = *(const float2*)(addc + (size_t)(gm + 8) * NDIM + gn);
        float2 bv = *(const float2*)(bias + gn);
        cb[nt][0] = c0.x + bv.x;
        cb[nt][1] = c0.y + bv.y;
        cb[nt][2] = c1.x + bv.x;
        cb[nt][3] = c1.y + bv.y;
    }

    if (tid == 0) {
        #pragma unroll
        for (int s = 0; s < STAGES; ++s) {
            mbar_init(fullA(s), 1);
            mbar_init(fullB(s), 1);
            mbar_init(emptyb(s), NWARP);
        }
        asm volatile("fence.proxy.async.shared::cta;" ::: "memory");
    }
    __syncthreads();

    const int8_t* Ab = A + (size_t)mblk * BLK_B;

    // issueA: waits slot free, expects+copies the 16KB A (weight) group
    auto issueA = [&](int j) {
        const int s = j % STAGES;
        if (j >= STAGES)
            mbar_wait_relaxed(emptyb(s), (uint32_t)((j / STAGES - 1) & 1));
        const uint32_t dst = sbase + SM_STAGE0 + s * STAGE_BYTES;
        mbar_expect_tx(fullA(s), 2 * KT_B);
        bulkcp(dst, Ab + (size_t)(2 * (j % NIT)) * KT_B, 2 * KT_B, fullA(s));
    };
    // issueB: expects+copies the 16KB B (h) group; slot already reserved by A
    auto issueB = [&](int j, const int8_t* Bblob) {
        const int s = j % STAGES;
        const uint32_t dst = sbase + SM_STAGE0 + s * STAGE_BYTES + 2 * KT_B;
        mbar_expect_tx(fullB(s), 2 * KT_B);
        bulkcp(dst, Bblob + (size_t)nblk * BLK_B + (size_t)(2 * (j % NIT)) * KT_B,
               2 * KT_B, fullB(s));
    };

    if (tid == 0) {
        #pragma unroll
        for (int p = 0; p < PREF; ++p) { issueA(p); issueB(p, hb0); }
    }

    for (int t = 0; t < NSTEPS; ++t) {
        const int8_t* Bb  = (t & 1) ? hb1 : hb0;
        int8_t*       out = (t & 1) ? hb0 : hb1;
        const int base = t * NIT;

        int C1[2][4] = {};
        int C2[2][4] = {};

        for (int it = 0; it < NIT; ++it) {
            const int j = base + it;
            if (tid == 0 && it + PREF < NIT) {
                issueA(j + PREF);
                issueB(j + PREF, Bb);
            }
            const int s = j % STAGES;
            const uint32_t par = (uint32_t)((j / STAGES) & 1);
            mbar_wait(fullA(s), par);
            mbar_wait(fullB(s), par);

            const uint32_t st = sbase + SM_STAGE0 + s * STAGE_BYTES;
            #pragma unroll
            for (int h = 0; h < 2; ++h) {
                const uint32_t sA1 = st + h * KT_B;
                const uint32_t sB1 = st + 2 * KT_B + h * KT_B;
                #pragma unroll
                for (int kk = 0; kk < 2; ++kk) {
                    const uint32_t ka = ((kk * 32) | achk) ^ aswz;
                    const uint32_t kb2 = ((kk * 32) | bchk) ^ bswz;
                    uint32_t a1f[4], a2f[4], b1f[4], b2f[4];
                    ldsm_x4(a1f, sA1 + arow + ka);
                    ldsm_x4(a2f, sA1 + TILE_B + arow + ka);
                    ldsm_x4(b1f, sB1 + brow + kb2);
                    ldsm_x4(b2f, sB1 + TILE_B + brow + kb2);
                    #pragma unroll
                    for (int nt = 0; nt < 2; ++nt) {
                        mma_s8(C1[nt], a1f, &b1f[nt * 2]);
                        mma_s8(C2[nt], a1f, &b2f[nt * 2]);
                        mma_s8(C2[nt], a2f, &b1f[nt * 2]);
                    }
                }
            }
            if (lane == 0) mbar_arrive(emptyb(s));
        }

        // prefetch next step's WEIGHT stages now (no data dependency)
        if (tid == 0 && t + 1 < NSTEPS) {
            #pragma unroll
            for (int p = 0; p < PREF; ++p) issueA(base + NIT + p);
        }

        // ---- epilogue: h' = tanh(D + c + bh), quantize, write blob ----
        int8_t* stg = (int8_t*)sm + SM_STG;
        #pragma unroll
        for (int nt = 0; nt < 2; ++nt) {
            const int lr = wm0 + (lane >> 2);
            const int lc = wn0 + nt * 8 + 2 * (lane & 3);
            float vv[4];
            #pragma unroll
            for (int q = 0; q < 4; ++q)
                vv[q] = tanhf(sAB * ((float)C1[nt][q] +
                                     (float)C2[nt][q] * (1.0f / 256.0f)) +
                              cb[nt][q]) * 127.0f;
            #pragma unroll
            for (int q = 0; q < 4; ++q) {
                const int r = lr + (q >> 1) * 8;
                const int cc = lc + (q & 1);
                int8_t d1, d2;
                quant2(vv[q], d1, d2);
                const uint32_t o = tswz(cc, r);
                stg[o] = d1;
                stg[o + TILE_B] = d2;
            }
        }
        __syncthreads();
        int8_t* dstb = out + (size_t)nblk * BLK_B + (size_t)mblk * KT_B;
        *(uint4*)&dstb[tid * 16] = *(const uint4*)&stg[tid * 16];
        __syncthreads();

        // ---- global step barrier ----
        if (tid == 0) {
            __threadfence();
            atomicAdd(&g_bar, 1u);
            const unsigned target = 128u * (unsigned)(t + 1);
            unsigned v;
            do {
                asm volatile("ld.global.acquire.gpu.u32 %0, [%1];"
                             : "=r"(v) : "l"(&g_bar));
            } while (v < target);
        }
        __syncthreads();

        // now next step's h is globally visible: issue its B stages
        if (tid == 0 && t + 1 < NSTEPS) {
            const int8_t* nB = ((t + 1) & 1) ? hb1 : hb0;
            #pragma unroll
            for (int p = 0; p < PREF; ++p) issueB(base + NIT + p, nB);
        }
    }
}

// ---------------------------------------------------------------- softmax
__global__ __launch_bounds__(256) void softmax_kernel(
    const float* __restrict__ p, float* __restrict__ out)
{
    const int row  = blockIdx.x * 8 + (threadIdx.x >> 5);
    const int lane = threadIdx.x & 31;
    const float* pr = p + (size_t)row * NDIM;
    float v[8];
    float mx = -INFINITY;
    #pragma unroll
    for (int i = 0; i < 8; ++i) { v[i] = pr[lane + 32 * i]; mx = fmaxf(mx, v[i]); }
    #pragma unroll
    for (int o = 16; o > 0; o >>= 1) mx = fmaxf(mx, __shfl_xor_sync(~0u, mx, o));
    float s = 0.f;
    #pragma unroll
    for (int i = 0; i < 8; ++i) { v[i] = expf(v[i] - mx); s += v[i]; }
    #pragma unroll
    for (int o = 16; o > 0; o >>= 1) s += __shfl_xor_sync(~0u, s, o);
    const float inv = 1.0f / s;
    float* orow = out + (size_t)row * NDIM;
    #pragma unroll
    for (int i = 0; i < 8; ++i) orow[lane + 32 * i] = v[i] * inv;
}

// ---------------------------------------------------------------- launch
extern "C" void kernel_launch(void* const* d_in, const int* in_sizes, int n_in,
                              void* d_out, int out_size)
{
    const float* x   = (const float*)d_in[0];
    const float* Whx = (const float*)d_in[1];
    const float* Whh = (const float*)d_in[2];
    const float* Wph = (const float*)d_in[3];
    const float* bh  = (const float*)d_in[4];
    const float* bp  = (const float*)d_in[5];

    int8_t *whx, *whh, *wph, *xb, *h0, *h1;
    float *c, *p;
    int* maxbits;
    cudaGetSymbolAddress((void**)&whx, g_Whx);
    cudaGetSymbolAddress((void**)&whh, g_Whh);
    cudaGetSymbolAddress((void**)&wph, g_Wph);
    cudaGetSymbolAddress((void**)&xb,  g_x);
    cudaGetSymbolAddress((void**)&h0,  g_h0);
    cudaGetSymbolAddress((void**)&h1,  g_h1);
    cudaGetSymbolAddress((void**)&c,   g_c);
    cudaGetSymbolAddress((void**)&p,   g_p);
    cudaGetSymbolAddress((void**)&maxbits, g_maxbits);

    cudaFuncSetAttribute(rnn_gemm, cudaFuncAttributeMaxDynamicSharedMemorySize,
                         SMEM_BYTES);
    cudaFuncSetAttribute(rnn_steps, cudaFuncAttributeMaxDynamicSharedMemorySize,
                         SMEM_BYTES);

    reset_kernel<<<1, 32>>>();
    maxabs_kernel<<<dim3(2048, 4), 256>>>(Whx, Whh, Wph, x);
    quant_kernel<<<dim3((MDIM * KDIM + 255) / 256, 4), 256>>>(Whx, Whh, Wph, x);

    const dim3 grid(NDIM / BN, MDIM / BM);   // (4, 32) = 128 CTAs

    // c = Whx @ x
    rnn_gemm<<<grid, THREADS, SMEM_BYTES>>>(whx, xb, maxbits + 0, maxbits + 3,
                                            nullptr, c, 0);

    // step 1: h1 = tanh(c + bh) (h0 = 0) -> h blob 0
    first_step_kernel<<<(MDIM * NDIM + 255) / 256, 256>>>(c, bh, h0);

    // steps 2..256: persistent kernel (255 steps); final h in h1
    rnn_steps<<<grid, THREADS, SMEM_BYTES>>>(whh, h0, h1, maxbits + 1, c, bh);

    // p = Wph @ h + bp; softmax
    rnn_gemm<<<grid, THREADS, SMEM_BYTES>>>(wph, h1, maxbits + 2, nullptr,
                                            bp, p, 1);
    softmax_kernel<<<MDIM / 8, 256>>>(p, (float*)d_out);
}